// round 1
// baseline (speedup 1.0000x reference)
#include <cuda_runtime.h>

// ---------------- problem constants ----------------
#define N_U      20000
#define N_O      10000
#define CDIM     256
#define TXTD     1536
#define NCOLS    7
#define E_EDGES  10000
#define MAXP     16
#define NUM_NODES 30000
#define VOCAB    101

#define X_ROWS   210000              // (N_U + N_O) * NCOLS
#define X_ELEMS  53760000            // X_ROWS * 256
#define OFF_NODE 53760000
#define OFF_COL  53970000
#define OFF_TAB  54180000
#define OFF_F2P  54390000
#define OFF_NN   57750000            // single scalar: num_nodes

// ---------------- scratch (no allocations allowed) ----------------
__device__ int g_tbl[NUM_NODES * MAXP];
__device__ int g_cnt[N_O];

// ---------------- init scratch each launch (graph determinism) ----------------
__global__ void init_scratch_kernel() {
    int i = blockIdx.x * blockDim.x + threadIdx.x;
    if (i < NUM_NODES * MAXP) g_tbl[i] = -1;
    if (i < N_O) g_cnt[i] = 0;
}

// ---------------- edge -> stable first-16-parents table ----------------
// rank[e] = #{e' < e : child[e'] == child[e]}  (stable argsort semantics)
// Single block, chunked: intra-chunk rank via O(chunk^2) shared scan,
// cross-chunk via g_cnt, atomics applied only after ranks are read.
__global__ void edge_table_kernel(const int* __restrict__ edge_index) {
    __shared__ int s_child[256];
    int tid = threadIdx.x;
    for (int base = 0; base < E_EDGES; base += 256) {
        int i = base + tid;
        int c = -1, p = 0;
        if (i < E_EDGES) {
            c = edge_index[i];            // edge_index[0][i]
            p = edge_index[E_EDGES + i];  // edge_index[1][i]
        }
        s_child[tid] = c;
        __syncthreads();
        if (i < E_EDGES) {
            int r = g_cnt[c];
            #pragma unroll 4
            for (int j = 0; j < tid; j++) {
                if (s_child[j] == c) r++;
            }
            if (r < MAXP) {
                g_tbl[(N_U + c) * MAXP + r] = p;
            }
        }
        __syncthreads();
        if (i < E_EDGES) atomicAdd(&g_cnt[c], 1);
        __syncthreads();
    }
}

// ---------------- f2p gather: out rows (210000,16) ----------------
__global__ void f2p_gather_kernel(float* __restrict__ out) {
    int i = blockIdx.x * blockDim.x + threadIdx.x;
    if (i >= X_ROWS * MAXP) return;
    int row = i >> 4;
    int s   = i & (MAXP - 1);
    int node;
    if (row < NCOLS * N_U) node = row % N_U;
    else                   node = N_U + (row - NCOLS * N_U) % N_O;
    out[OFF_F2P + i] = (float)g_tbl[node * MAXP + s];
}

// ---------------- index arrays + num_nodes ----------------
__global__ void index_kernel(float* __restrict__ out) {
    int i = blockIdx.x * blockDim.x + threadIdx.x;
    if (i > 3 * X_ROWS) return;
    if (i == 3 * X_ROWS) { out[OFF_NN] = (float)NUM_NODES; return; }
    int r = i / X_ROWS;
    int j = i - r * X_ROWS;
    int node, colv, tabv;
    if (j < NCOLS * N_U) {
        node = j % N_U;         // tile(arange(N_U), NCOLS)
        colv = j / N_U;         // repeat(arange(NCOLS), N_U)
        tabv = 0;
    } else {
        int jj = j - NCOLS * N_U;
        node = N_U + jj % N_O;
        colv = NCOLS + jj / N_O;
        tabv = 1;
    }
    if      (r == 0) out[OFF_NODE + j] = (float)node;
    else if (r == 1) out[OFF_COL  + j] = (float)colv;
    else             out[OFF_TAB  + j] = (float)tabv;
}

// ---------------- num + cat tokens (k = 0..5) ----------------
// one block per (table, k, n) row; thread = channel c
__global__ void tok_kernel(
    const float* __restrict__ unum, const int* __restrict__ ucat,
    const float* __restrict__ onum, const int* __restrict__ ocat,
    const float* __restrict__ u_nw, const float* __restrict__ u_nb,
    const float* __restrict__ u_ct, const float* __restrict__ u_col,
    const float* __restrict__ o_nw, const float* __restrict__ o_nb,
    const float* __restrict__ o_ct, const float* __restrict__ o_col,
    const float* __restrict__ temb, float* __restrict__ out)
{
    int bid = blockIdx.x;
    int c = threadIdx.x;
    int k, n, row;
    const float *nw, *nb, *ct, *col, *te, *nump;
    const int* catp;
    if (bid < 6 * N_U) {
        k = bid / N_U; n = bid - k * N_U;
        row = k * N_U + n;
        nw = u_nw; nb = u_nb; ct = u_ct; col = u_col; te = temb;
        nump = unum; catp = ucat;
    } else {
        int b = bid - 6 * N_U;
        k = b / N_O; n = b - k * N_O;
        row = NCOLS * N_U + k * N_O + n;
        nw = o_nw; nb = o_nb; ct = o_ct; col = o_col; te = temb + CDIM;
        nump = onum; catp = ocat;
    }
    float v;
    if (k < 3) {
        float z = nump[n * 3 + k] * nw[k * CDIM + c] + nb[k * CDIM + c];
        v = z / (1.0f + __expf(-z));   // silu
    } else {
        int idx = catp[n * 3 + (k - 3)];
        v = ct[((k - 3) * VOCAB + idx) * CDIM + c];
    }
    v += col[k * CDIM + c] + te[c];
    out[row * CDIM + c] = v;
}

// ---------------- text GEMM: out[m,c] = dot(A[m,:TXTD], W[c,:TXTD]) + bias(c) ----------------
// fp32 SIMT tiled: BM=128, BN=64, BK=16, 256 threads, 8x4 microtile
#define BM 128
#define BN 64
#define BK 16

__global__ void txt_gemm_kernel(
    const float* __restrict__ A,    // [M, 1536]
    const float* __restrict__ W,    // [256, 1536]
    const float* __restrict__ tb,   // [256]
    const float* __restrict__ col6, // [256]
    const float* __restrict__ te,   // [256]
    float* __restrict__ out, int M, int out_row0)
{
    __shared__ float As[BK][BM + 1];
    __shared__ float Bs[BK][BN + 4];

    int tid = threadIdx.x;
    int tx = tid & 15;
    int ty = tid >> 4;
    int block_m = blockIdx.x * BM;
    int block_n = blockIdx.y * BN;

    float acc[8][4];
    #pragma unroll
    for (int i = 0; i < 8; i++)
        #pragma unroll
        for (int j = 0; j < 4; j++) acc[i][j] = 0.0f;

    for (int k0 = 0; k0 < TXTD; k0 += BK) {
        // load A tile: 128 rows x 16 cols = 512 float4
        #pragma unroll
        for (int r = 0; r < 2; r++) {
            int idx = tid + r * 256;       // 0..511
            int row = idx >> 2;            // 0..127
            int kk4 = (idx & 3) * 4;       // 0,4,8,12
            float4 v = make_float4(0.f, 0.f, 0.f, 0.f);
            int gm = block_m + row;
            if (gm < M) v = *(const float4*)&A[(size_t)gm * TXTD + k0 + kk4];
            As[kk4 + 0][row] = v.x;
            As[kk4 + 1][row] = v.y;
            As[kk4 + 2][row] = v.z;
            As[kk4 + 3][row] = v.w;
        }
        // load W tile: 64 rows x 16 cols = 256 float4
        {
            int row = tid >> 2;
            int kk4 = (tid & 3) * 4;
            float4 v = *(const float4*)&W[(size_t)(block_n + row) * TXTD + k0 + kk4];
            Bs[kk4 + 0][row] = v.x;
            Bs[kk4 + 1][row] = v.y;
            Bs[kk4 + 2][row] = v.z;
            Bs[kk4 + 3][row] = v.w;
        }
        __syncthreads();

        #pragma unroll
        for (int kk = 0; kk < BK; kk++) {
            float a[8], b[4];
            #pragma unroll
            for (int i = 0; i < 8; i++) a[i] = As[kk][ty * 8 + i];
            #pragma unroll
            for (int j = 0; j < 4; j++) b[j] = Bs[kk][tx * 4 + j];
            #pragma unroll
            for (int i = 0; i < 8; i++)
                #pragma unroll
                for (int j = 0; j < 4; j++)
                    acc[i][j] = fmaf(a[i], b[j], acc[i][j]);
        }
        __syncthreads();
    }

    // epilogue: + txt_b + col[6] + table_emb
    #pragma unroll
    for (int i = 0; i < 8; i++) {
        int gm = block_m + ty * 8 + i;
        if (gm >= M) continue;
        #pragma unroll
        for (int j = 0; j < 4; j++) {
            int c = block_n + tx * 4 + j;
            out[(size_t)(out_row0 + gm) * CDIM + c] =
                acc[i][j] + tb[c] + col6[c] + te[c];
        }
    }
}

// ---------------- launch ----------------
extern "C" void kernel_launch(void* const* d_in, const int* in_sizes, int n_in,
                              void* d_out, int out_size) {
    const float* users_num   = (const float*)d_in[0];
    const int*   users_cat   = (const int*)  d_in[1];
    const float* users_text  = (const float*)d_in[2];
    const float* orders_num  = (const float*)d_in[3];
    const int*   orders_cat  = (const int*)  d_in[4];
    const float* orders_text = (const float*)d_in[5];
    const int*   edge_index  = (const int*)  d_in[6];
    const float* table_emb   = (const float*)d_in[7];
    const float* u_num_w     = (const float*)d_in[8];
    const float* u_num_b     = (const float*)d_in[9];
    const float* u_cat_tab   = (const float*)d_in[10];
    const float* u_txt_w     = (const float*)d_in[11];
    const float* u_txt_b     = (const float*)d_in[12];
    const float* u_col       = (const float*)d_in[13];
    const float* o_num_w     = (const float*)d_in[14];
    const float* o_num_b     = (const float*)d_in[15];
    const float* o_cat_tab   = (const float*)d_in[16];
    const float* o_txt_w     = (const float*)d_in[17];
    const float* o_txt_b     = (const float*)d_in[18];
    const float* o_col       = (const float*)d_in[19];

    float* out = (float*)d_out;

    // scratch init + edge table + f2p gather
    init_scratch_kernel<<<(NUM_NODES * MAXP + 255) / 256, 256>>>();
    edge_table_kernel<<<1, 256>>>(edge_index);
    f2p_gather_kernel<<<(X_ROWS * MAXP + 255) / 256, 256>>>(out);

    // index arrays + num_nodes scalar
    index_kernel<<<(3 * X_ROWS + 1 + 255) / 256, 256>>>(out);

    // num + cat tokens (k = 0..5, both tables)
    tok_kernel<<<6 * N_U + 6 * N_O, CDIM>>>(
        users_num, users_cat, orders_num, orders_cat,
        u_num_w, u_num_b, u_cat_tab, u_col,
        o_num_w, o_num_b, o_cat_tab, o_col,
        table_emb, out);

    // text GEMM for users (k=6 rows at 6*N_U) and orders (rows at NCOLS*N_U + 6*N_O)
    {
        dim3 grid_u((N_U + BM - 1) / BM, CDIM / BN);
        txt_gemm_kernel<<<grid_u, 256>>>(
            users_text, u_txt_w, u_txt_b, u_col + 6 * CDIM, table_emb,
            out, N_U, 6 * N_U);
        dim3 grid_o((N_O + BM - 1) / BM, CDIM / BN);
        txt_gemm_kernel<<<grid_o, 256>>>(
            orders_text, o_txt_w, o_txt_b, o_col + 6 * CDIM, table_emb + CDIM,
            out, N_O, NCOLS * N_U + 6 * N_O);
    }
}

// round 3
// speedup vs baseline: 1.4969x; 1.4969x over previous
#include <cuda_runtime.h>
#include <cuda_bf16.h>
#include <cstdint>

// ---------------- problem constants ----------------
#define N_U      20000
#define N_O      10000
#define CDIM     256
#define TXTD     1536
#define NCOLS    7
#define E_EDGES  10000
#define MAXP     16
#define NUM_NODES 30000
#define VOCAB    101

#define X_ROWS   210000
#define OFF_NODE 53760000
#define OFF_COL  53970000
#define OFF_TAB  54180000
#define OFF_F2P  54390000
#define OFF_NN   57750000

// ---------------- device scratch ----------------
__device__ int g_tbl[NUM_NODES * MAXP];
__device__ int g_cnt[N_O];
__device__ __nv_bfloat16 g_w_hi[2 * CDIM * TXTD];   // rows 0..255 users, 256..511 orders
__device__ __nv_bfloat16 g_w_lo[2 * CDIM * TXTD];

// ---------------- helpers ----------------
__device__ __forceinline__ uint32_t smem_u32(const void* p) {
    uint32_t a;
    asm("{ .reg .u64 t; cvta.to.shared.u64 t, %1; cvt.u32.u64 %0, t; }" : "=r"(a) : "l"(p));
    return a;
}

__device__ __forceinline__ void split2(float a, float b, uint32_t& h, uint32_t& l) {
    __nv_bfloat162 hb = __floats2bfloat162_rn(a, b);
    float fa = __bfloat162float(hb.x);
    float fb = __bfloat162float(hb.y);
    __nv_bfloat162 lb = __floats2bfloat162_rn(a - fa, b - fb);
    h = *reinterpret_cast<uint32_t*>(&hb);
    l = *reinterpret_cast<uint32_t*>(&lb);
}

#define LDSM_X4(r0, r1, r2, r3, addr) \
    asm volatile("ldmatrix.sync.aligned.m8n8.x4.shared.b16 {%0,%1,%2,%3}, [%4];" \
        : "=r"(r0), "=r"(r1), "=r"(r2), "=r"(r3) : "r"(addr))

#define MMA16816(d, a, b0, b1) \
    asm volatile("mma.sync.aligned.m16n8k16.row.col.f32.bf16.bf16.f32 " \
        "{%0,%1,%2,%3}, {%4,%5,%6,%7}, {%8,%9}, {%0,%1,%2,%3};" \
        : "+f"((d)[0]), "+f"((d)[1]), "+f"((d)[2]), "+f"((d)[3]) \
        : "r"((a)[0]), "r"((a)[1]), "r"((a)[2]), "r"((a)[3]), "r"(b0), "r"(b1))

// ---------------- init scratch ----------------
__global__ void init_scratch_kernel() {
    int i = blockIdx.x * blockDim.x + threadIdx.x;
    if (i < NUM_NODES * MAXP) g_tbl[i] = -1;
    if (i < N_O) g_cnt[i] = 0;
}

// ---------------- W split: fp32 -> bf16 hi/lo ----------------
__global__ void w_split_kernel(const float* __restrict__ uw, const float* __restrict__ ow) {
    int i = blockIdx.x * blockDim.x + threadIdx.x;   // pair index
    if (i >= CDIM * TXTD) return;
    int idx = i * 2;
    float a, b;
    if (idx < CDIM * TXTD) { a = uw[idx]; b = uw[idx + 1]; }
    else { a = ow[idx - CDIM * TXTD]; b = ow[idx - CDIM * TXTD + 1]; }
    uint32_t h, l;
    split2(a, b, h, l);
    *(uint32_t*)&g_w_hi[idx] = h;
    *(uint32_t*)&g_w_lo[idx] = l;
}

// ---------------- edge -> stable first-16-parents table ----------------
__global__ void edge_table_kernel(const int* __restrict__ edge_index) {
    __shared__ int s_child[256];
    int tid = threadIdx.x;
    for (int base = 0; base < E_EDGES; base += 256) {
        int i = base + tid;
        int c = -1, p = 0;
        if (i < E_EDGES) {
            c = edge_index[i];
            p = edge_index[E_EDGES + i];
        }
        s_child[tid] = c;
        __syncthreads();
        if (i < E_EDGES) {
            int r = g_cnt[c];
            #pragma unroll 4
            for (int j = 0; j < tid; j++)
                if (s_child[j] == c) r++;
            if (r < MAXP) g_tbl[(N_U + c) * MAXP + r] = p;
        }
        __syncthreads();
        if (i < E_EDGES) atomicAdd(&g_cnt[c], 1);
        __syncthreads();
    }
}

// ---------------- f2p gather ----------------
__global__ void f2p_gather_kernel(float* __restrict__ out) {
    int i = blockIdx.x * blockDim.x + threadIdx.x;
    if (i >= X_ROWS * MAXP) return;
    int row = i >> 4;
    int s = i & (MAXP - 1);
    int node;
    if (row < NCOLS * N_U) node = row % N_U;
    else                   node = N_U + (row - NCOLS * N_U) % N_O;
    out[OFF_F2P + i] = (float)g_tbl[node * MAXP + s];
}

// ---------------- index arrays + num_nodes ----------------
__global__ void index_kernel(float* __restrict__ out) {
    int i = blockIdx.x * blockDim.x + threadIdx.x;
    if (i > 3 * X_ROWS) return;
    if (i == 3 * X_ROWS) { out[OFF_NN] = (float)NUM_NODES; return; }
    int r = i / X_ROWS;
    int j = i - r * X_ROWS;
    int node, colv, tabv;
    if (j < NCOLS * N_U) {
        node = j % N_U; colv = j / N_U; tabv = 0;
    } else {
        int jj = j - NCOLS * N_U;
        node = N_U + jj % N_O; colv = NCOLS + jj / N_O; tabv = 1;
    }
    if      (r == 0) out[OFF_NODE + j] = (float)node;
    else if (r == 1) out[OFF_COL  + j] = (float)colv;
    else             out[OFF_TAB  + j] = (float)tabv;
}

// ---------------- num + cat tokens ----------------
__global__ void tok_kernel(
    const float* __restrict__ unum, const int* __restrict__ ucat,
    const float* __restrict__ onum, const int* __restrict__ ocat,
    const float* __restrict__ u_nw, const float* __restrict__ u_nb,
    const float* __restrict__ u_ct, const float* __restrict__ u_col,
    const float* __restrict__ o_nw, const float* __restrict__ o_nb,
    const float* __restrict__ o_ct, const float* __restrict__ o_col,
    const float* __restrict__ temb, float* __restrict__ out)
{
    int bid = blockIdx.x;
    int c = threadIdx.x;
    int k, n, row;
    const float *nw, *nb, *ct, *col, *te, *nump;
    const int* catp;
    if (bid < 6 * N_U) {
        k = bid / N_U; n = bid - k * N_U;
        row = k * N_U + n;
        nw = u_nw; nb = u_nb; ct = u_ct; col = u_col; te = temb;
        nump = unum; catp = ucat;
    } else {
        int b = bid - 6 * N_U;
        k = b / N_O; n = b - k * N_O;
        row = NCOLS * N_U + k * N_O + n;
        nw = o_nw; nb = o_nb; ct = o_ct; col = o_col; te = temb + CDIM;
        nump = onum; catp = ocat;
    }
    float v;
    if (k < 3) {
        float z = nump[n * 3 + k] * nw[k * CDIM + c] + nb[k * CDIM + c];
        v = z / (1.0f + __expf(-z));
    } else {
        int idx = catp[n * 3 + (k - 3)];
        v = ct[((k - 3) * VOCAB + idx) * CDIM + c];
    }
    v += col[k * CDIM + c] + te[c];
    out[row * CDIM + c] = v;
}

// ---------------- mma.sync bf16 text GEMM ----------------
// CTA tile: 128 rows x 128 cols (N-half), K streamed in 32-chunks.
// 256 threads = 8 warps laid out 4(m) x 2(n); warp tile 32x64.
// SMEM tiles: row stride 80B (conflict-free ldmatrix without swizzle).
#define U_TILES 157
#define O_TILES 79
#define NTILES  (U_TILES + O_TILES)
#define BK      32
#define ROWB    80    // bytes per smem tile row (32 bf16 = 64B + 16B pad)

__global__ void __launch_bounds__(256) txt_gemm_mma(
    const float* __restrict__ uA, const float* __restrict__ oA,
    const float* __restrict__ u_tb, const float* __restrict__ u_col,
    const float* __restrict__ o_tb, const float* __restrict__ o_col,
    const float* __restrict__ temb, float* __restrict__ out)
{
    __shared__ char s_ahi[128 * ROWB];
    __shared__ char s_alo[128 * ROWB];
    __shared__ char s_bhi[128 * ROWB];
    __shared__ char s_blo[128 * ROWB];
    __shared__ float s_bias[128];

    int tid = threadIdx.x;
    int lane = tid & 31;
    int wid = tid >> 5;
    int warp_m = wid & 3;        // 0..3 -> 32-row slice
    int warp_n = wid >> 2;       // 0..1 -> 64-col slice

    int tile = blockIdx.x;
    int half = blockIdx.y;       // 0/1 -> N cols [0,128) / [128,256)

    const float* A;
    int M, m0, orow0, wrow0;
    const float *tb, *col, *te;
    if (tile < U_TILES) {
        A = uA; M = N_U; m0 = tile * 128; orow0 = 6 * N_U; wrow0 = 0;
        tb = u_tb; col = u_col; te = temb;
    } else {
        A = oA; M = N_O; m0 = (tile - U_TILES) * 128;
        orow0 = NCOLS * N_U + 6 * N_O; wrow0 = CDIM;
        tb = o_tb; col = o_col; te = temb + CDIM;
    }
    int ncol0 = half * 128;      // CTA's first global output column
    int brow0 = wrow0 + ncol0;   // first W row for this CTA

    // bias for this CTA's 128 columns
    if (tid < 128) {
        int c = ncol0 + tid;
        s_bias[tid] = tb[c] + col[6 * CDIM + c] + te[c];
    }

    float acc[2][8][4];
    #pragma unroll
    for (int mi = 0; mi < 2; mi++)
        #pragma unroll
        for (int nt = 0; nt < 8; nt++)
            #pragma unroll
            for (int q = 0; q < 4; q++) acc[mi][nt][q] = 0.0f;

    uint32_t sa_hi = smem_u32(s_ahi), sa_lo = smem_u32(s_alo);
    uint32_t sb_hi = smem_u32(s_bhi), sb_lo = smem_u32(s_blo);

    // ldmatrix lane-invariant address parts
    // A x4: row = warp_m*32 + mi*16 + (lane&15); chunk = 2*ks + (lane>>4)
    uint32_t a_row = (uint32_t)(warp_m * 32 + (lane & 15));
    uint32_t a_ch  = (uint32_t)(lane >> 4);
    // B x4: n = warp_n*64 + np*16 + (lane&7) + ((lane>>4)<<3); chunk = 2*ks + ((lane>>3)&1)
    uint32_t b_row = (uint32_t)(warp_n * 64 + (lane & 7) + ((lane >> 4) << 3));
    uint32_t b_ch  = (uint32_t)((lane >> 3) & 1);

    for (int ch = 0; ch < TXTD / BK; ch++) {
        int k0 = ch * BK;

        // ---- load A: 128 rows x 32 fp32 -> hi/lo bf16 smem ----
        #pragma unroll
        for (int gg = 0; gg < 2; gg++) {
            int g = tid + gg * 256;       // 0..511
            int r = g >> 2, cs = g & 3;   // row, 8-col segment
            int gm = m0 + r;
            float4 v0 = make_float4(0.f, 0.f, 0.f, 0.f);
            float4 v1 = make_float4(0.f, 0.f, 0.f, 0.f);
            if (gm < M) {
                const float* p = A + (size_t)gm * TXTD + k0 + cs * 8;
                v0 = *(const float4*)p;
                v1 = *(const float4*)(p + 4);
            }
            uint4 h, l;
            split2(v0.x, v0.y, h.x, l.x);
            split2(v0.z, v0.w, h.y, l.y);
            split2(v1.x, v1.y, h.z, l.z);
            split2(v1.z, v1.w, h.w, l.w);
            int off = r * ROWB + cs * 16;
            *(uint4*)(s_ahi + off) = h;
            *(uint4*)(s_alo + off) = l;
        }
        // ---- load B: 128 rows x 32 bf16 hi/lo from pre-split W ----
        #pragma unroll
        for (int gg = 0; gg < 2; gg++) {
            int g = tid + gg * 256;       // 0..511
            int r = g >> 2, cs = g & 3;
            size_t gi = (size_t)(brow0 + r) * TXTD + k0 + cs * 8;
            int off = r * ROWB + cs * 16;
            *(uint4*)(s_bhi + off) = *(const uint4*)&g_w_hi[gi];
            *(uint4*)(s_blo + off) = *(const uint4*)&g_w_lo[gi];
        }
        __syncthreads();

        // ---- MMA: 2 k-steps x (hi*hi + lo*hi + hi*lo) ----
        #pragma unroll
        for (int ks = 0; ks < 2; ks++) {
            uint32_t a_off = a_row * ROWB + (2 * ks + a_ch) * 16;
            uint32_t b_off = b_row * ROWB + (2 * ks + b_ch) * 16;

            uint32_t ah[2][4], bh[4][4];
            #pragma unroll
            for (int mi = 0; mi < 2; mi++)
                LDSM_X4(ah[mi][0], ah[mi][1], ah[mi][2], ah[mi][3],
                        sa_hi + a_off + mi * 16 * ROWB);
            #pragma unroll
            for (int np = 0; np < 4; np++)
                LDSM_X4(bh[np][0], bh[np][1], bh[np][2], bh[np][3],
                        sb_hi + b_off + np * 16 * ROWB);
            #pragma unroll
            for (int mi = 0; mi < 2; mi++)
                #pragma unroll
                for (int np = 0; np < 4; np++) {
                    MMA16816(acc[mi][2 * np],     ah[mi], bh[np][0], bh[np][1]);
                    MMA16816(acc[mi][2 * np + 1], ah[mi], bh[np][2], bh[np][3]);
                }

            uint32_t al[2][4];
            #pragma unroll
            for (int mi = 0; mi < 2; mi++)
                LDSM_X4(al[mi][0], al[mi][1], al[mi][2], al[mi][3],
                        sa_lo + a_off + mi * 16 * ROWB);
            #pragma unroll
            for (int mi = 0; mi < 2; mi++)
                #pragma unroll
                for (int np = 0; np < 4; np++) {
                    MMA16816(acc[mi][2 * np],     al[mi], bh[np][0], bh[np][1]);
                    MMA16816(acc[mi][2 * np + 1], al[mi], bh[np][2], bh[np][3]);
                }

            uint32_t bl[4][4];
            #pragma unroll
            for (int np = 0; np < 4; np++)
                LDSM_X4(bl[np][0], bl[np][1], bl[np][2], bl[np][3],
                        sb_lo + b_off + np * 16 * ROWB);
            #pragma unroll
            for (int mi = 0; mi < 2; mi++)
                #pragma unroll
                for (int np = 0; np < 4; np++) {
                    MMA16816(acc[mi][2 * np],     ah[mi], bl[np][0], bl[np][1]);
                    MMA16816(acc[mi][2 * np + 1], ah[mi], bl[np][2], bl[np][3]);
                }
        }
        __syncthreads();
    }

    // ---- epilogue: direct stores with bias ----
    #pragma unroll
    for (int mi = 0; mi < 2; mi++) {
        #pragma unroll
        for (int rh = 0; rh < 2; rh++) {
            int row = m0 + warp_m * 32 + mi * 16 + (lane >> 2) + rh * 8;
            if (row >= M) continue;
            size_t rbase = (size_t)(orow0 + row) * CDIM + ncol0;
            #pragma unroll
            for (int nt = 0; nt < 8; nt++) {
                int cc = warp_n * 64 + nt * 8 + (lane & 3) * 2;  // CTA-local col
                float2 o;
                o.x = acc[mi][nt][rh * 2 + 0] + s_bias[cc];
                o.y = acc[mi][nt][rh * 2 + 1] + s_bias[cc + 1];
                *(float2*)&out[rbase + cc] = o;
            }
        }
    }
}

// ---------------- launch ----------------
extern "C" void kernel_launch(void* const* d_in, const int* in_sizes, int n_in,
                              void* d_out, int out_size) {
    const float* users_num   = (const float*)d_in[0];
    const int*   users_cat   = (const int*)  d_in[1];
    const float* users_text  = (const float*)d_in[2];
    const float* orders_num  = (const float*)d_in[3];
    const int*   orders_cat  = (const int*)  d_in[4];
    const float* orders_text = (const float*)d_in[5];
    const int*   edge_index  = (const int*)  d_in[6];
    const float* table_emb   = (const float*)d_in[7];
    const float* u_num_w     = (const float*)d_in[8];
    const float* u_num_b     = (const float*)d_in[9];
    const float* u_cat_tab   = (const float*)d_in[10];
    const float* u_txt_w     = (const float*)d_in[11];
    const float* u_txt_b     = (const float*)d_in[12];
    const float* u_col       = (const float*)d_in[13];
    const float* o_num_w     = (const float*)d_in[14];
    const float* o_num_b     = (const float*)d_in[15];
    const float* o_cat_tab   = (const float*)d_in[16];
    const float* o_txt_w     = (const float*)d_in[17];
    const float* o_txt_b     = (const float*)d_in[18];
    const float* o_col       = (const float*)d_in[19];

    float* out = (float*)d_out;

    // W hi/lo split (tiny, feeds the GEMM)
    w_split_kernel<<<(CDIM * TXTD + 255) / 256, 256>>>(u_txt_w, o_txt_w);

    // tensor-core (HMMA) text GEMM
    {
        dim3 grid(NTILES, 2);
        txt_gemm_mma<<<grid, 256>>>(
            users_text, orders_text,
            u_txt_b, u_col, o_txt_b, o_col, table_emb, out);
    }

    // scratch init + edge table + f2p gather
    init_scratch_kernel<<<(NUM_NODES * MAXP + 255) / 256, 256>>>();
    edge_table_kernel<<<1, 256>>>(edge_index);
    f2p_gather_kernel<<<(X_ROWS * MAXP + 255) / 256, 256>>>(out);

    // index arrays + num_nodes scalar
    index_kernel<<<(3 * X_ROWS + 1 + 255) / 256, 256>>>(out);

    // num + cat tokens
    tok_kernel<<<6 * N_U + 6 * N_O, CDIM>>>(
        users_num, users_cat, orders_num, orders_cat,
        u_num_w, u_num_b, u_cat_tab, u_col,
        o_num_w, o_num_b, o_cat_tab, o_col,
        table_emb, out);
}

// round 4
// speedup vs baseline: 2.5756x; 1.7206x over previous
#include <cuda_runtime.h>
#include <cuda_bf16.h>
#include <cstdint>

// ---------------- problem constants ----------------
#define N_U      20000
#define N_O      10000
#define N_TOT    30000
#define CDIM     256
#define TXTD     1536
#define NCOLS    7
#define E_EDGES  10000
#define MAXP     16
#define NUM_NODES 30000
#define VOCAB    101

#define X_ROWS   210000
#define OFF_NODE 53760000
#define OFF_COL  53970000
#define OFF_TAB  54180000
#define OFF_F2P  54390000
#define OFF_NN   57750000

// ---------------- device scratch ----------------
__device__ int g_tbl[NUM_NODES * MAXP];
__device__ int g_cnt[N_O];
__device__ int g_slot[N_O * 32];
__device__ __nv_bfloat16 g_w_hi[2 * CDIM * TXTD];
__device__ __nv_bfloat16 g_w_lo[2 * CDIM * TXTD];
__device__ __nv_bfloat16 g_a_hi[(size_t)N_TOT * TXTD];   // rows: 0..19999 users, 20000.. orders
__device__ __nv_bfloat16 g_a_lo[(size_t)N_TOT * TXTD];

// ---------------- helpers ----------------
__device__ __forceinline__ uint32_t smem_u32(const void* p) {
    uint32_t a;
    asm("{ .reg .u64 t; cvta.to.shared.u64 t, %1; cvt.u32.u64 %0, t; }" : "=r"(a) : "l"(p));
    return a;
}

__device__ __forceinline__ void split2(float a, float b, uint32_t& h, uint32_t& l) {
    __nv_bfloat162 hb = __floats2bfloat162_rn(a, b);
    float fa = __bfloat162float(hb.x);
    float fb = __bfloat162float(hb.y);
    __nv_bfloat162 lb = __floats2bfloat162_rn(a - fa, b - fb);
    h = *reinterpret_cast<uint32_t*>(&hb);
    l = *reinterpret_cast<uint32_t*>(&lb);
}

#define LDSM_X4(r0, r1, r2, r3, addr) \
    asm volatile("ldmatrix.sync.aligned.m8n8.x4.shared.b16 {%0,%1,%2,%3}, [%4];" \
        : "=r"(r0), "=r"(r1), "=r"(r2), "=r"(r3) : "r"(addr))

#define MMA16816(d, a, b0, b1) \
    asm volatile("mma.sync.aligned.m16n8k16.row.col.f32.bf16.bf16.f32 " \
        "{%0,%1,%2,%3}, {%4,%5,%6,%7}, {%8,%9}, {%0,%1,%2,%3};" \
        : "+f"((d)[0]), "+f"((d)[1]), "+f"((d)[2]), "+f"((d)[3]) \
        : "r"((a)[0]), "r"((a)[1]), "r"((a)[2]), "r"((a)[3]), "r"(b0), "r"(b1))

__device__ __forceinline__ void cp16(uint32_t dst, const void* src, int pred_sz) {
    asm volatile("cp.async.cg.shared.global [%0], [%1], 16, %2;"
                 :: "r"(dst), "l"(src), "r"(pred_sz));
}
#define CP_COMMIT() asm volatile("cp.async.commit_group;" ::: "memory")
#define CP_WAIT1()  asm volatile("cp.async.wait_group 1;" ::: "memory")
#define CP_WAIT0()  asm volatile("cp.async.wait_group 0;" ::: "memory")

// ---------------- init scratch ----------------
__global__ void init_scratch_kernel() {
    int i = blockIdx.x * blockDim.x + threadIdx.x;
    if (i < NUM_NODES * MAXP) g_tbl[i] = -1;
    if (i < N_O) g_cnt[i] = 0;
}

// ---------------- W split ----------------
__global__ void w_split_kernel(const float* __restrict__ uw, const float* __restrict__ ow) {
    int i = blockIdx.x * blockDim.x + threadIdx.x;
    if (i >= CDIM * TXTD) return;
    int idx = i * 2;
    float a, b;
    if (idx < CDIM * TXTD) { a = uw[idx]; b = uw[idx + 1]; }
    else { a = ow[idx - CDIM * TXTD]; b = ow[idx - CDIM * TXTD + 1]; }
    uint32_t h, l;
    split2(a, b, h, l);
    *(uint32_t*)&g_w_hi[idx] = h;
    *(uint32_t*)&g_w_lo[idx] = l;
}

// ---------------- A split: fp32 -> bf16 hi/lo (combined users+orders) ----------------
#define U_ELE (N_U * TXTD)
__global__ void a_split_kernel(const float* __restrict__ u, const float* __restrict__ o) {
    size_t i4 = ((size_t)blockIdx.x * blockDim.x + threadIdx.x) * 4;
    if (i4 >= (size_t)N_TOT * TXTD) return;
    const float* src = (i4 < U_ELE) ? (u + i4) : (o + (i4 - U_ELE));
    float4 v = *(const float4*)src;
    uint2 h, l;
    split2(v.x, v.y, h.x, l.x);
    split2(v.z, v.w, h.y, l.y);
    *(uint2*)&g_a_hi[i4] = h;
    *(uint2*)&g_a_lo[i4] = l;
}

// ---------------- edges: scatter + per-child sort (stable, deterministic) ----------------
__global__ void edge_scatter_kernel(const int* __restrict__ edge_index) {
    int i = blockIdx.x * blockDim.x + threadIdx.x;
    if (i >= E_EDGES) return;
    int c = edge_index[i];
    int s = atomicAdd(&g_cnt[c], 1);
    if (s < 32) g_slot[c * 32 + s] = i;
}

__global__ void edge_sort_write_kernel(const int* __restrict__ edge_index) {
    int c = blockIdx.x * blockDim.x + threadIdx.x;
    if (c >= N_O) return;
    int n = g_cnt[c];
    if (n > 32) n = 32;
    int idx[32];
    for (int j = 0; j < n; j++) {
        int v = g_slot[c * 32 + j];
        int pos = j;
        while (pos > 0 && idx[pos - 1] > v) { idx[pos] = idx[pos - 1]; pos--; }
        idx[pos] = v;
    }
    int lim = n < MAXP ? n : MAXP;
    for (int r = 0; r < lim; r++)
        g_tbl[(N_U + c) * MAXP + r] = edge_index[E_EDGES + idx[r]];
}

// ---------------- f2p gather ----------------
__global__ void f2p_gather_kernel(float* __restrict__ out) {
    int i = blockIdx.x * blockDim.x + threadIdx.x;
    if (i >= X_ROWS * MAXP) return;
    int row = i >> 4;
    int s = i & (MAXP - 1);
    int node;
    if (row < NCOLS * N_U) node = row % N_U;
    else                   node = N_U + (row - NCOLS * N_U) % N_O;
    out[OFF_F2P + i] = (float)g_tbl[node * MAXP + s];
}

// ---------------- index arrays + num_nodes ----------------
__global__ void index_kernel(float* __restrict__ out) {
    int i = blockIdx.x * blockDim.x + threadIdx.x;
    if (i > 3 * X_ROWS) return;
    if (i == 3 * X_ROWS) { out[OFF_NN] = (float)NUM_NODES; return; }
    int r = i / X_ROWS;
    int j = i - r * X_ROWS;
    int node, colv, tabv;
    if (j < NCOLS * N_U) {
        node = j % N_U; colv = j / N_U; tabv = 0;
    } else {
        int jj = j - NCOLS * N_U;
        node = N_U + jj % N_O; colv = NCOLS + jj / N_O; tabv = 1;
    }
    if      (r == 0) out[OFF_NODE + j] = (float)node;
    else if (r == 1) out[OFF_COL  + j] = (float)colv;
    else             out[OFF_TAB  + j] = (float)tabv;
}

// ---------------- num + cat tokens (vectorized: 4 rows/block, float4/thread) ----------------
__global__ void tok_kernel(
    const float* __restrict__ unum, const int* __restrict__ ucat,
    const float* __restrict__ onum, const int* __restrict__ ocat,
    const float* __restrict__ u_nw, const float* __restrict__ u_nb,
    const float* __restrict__ u_ct, const float* __restrict__ u_col,
    const float* __restrict__ o_nw, const float* __restrict__ o_nb,
    const float* __restrict__ o_ct, const float* __restrict__ o_col,
    const float* __restrict__ temb, float* __restrict__ out)
{
    // 64 threads per row (float4 each), 4 rows per block
    int rid = blockIdx.x * 4 + (threadIdx.x >> 6);
    int c4 = (threadIdx.x & 63) * 4;
    int k, n, row;
    const float *nw, *nb, *ct, *col, *te, *nump;
    const int* catp;
    if (rid < 6 * N_U) {
        k = rid / N_U; n = rid - k * N_U;
        row = k * N_U + n;
        nw = u_nw; nb = u_nb; ct = u_ct; col = u_col; te = temb;
        nump = unum; catp = ucat;
    } else {
        int b = rid - 6 * N_U;
        k = b / N_O; n = b - k * N_O;
        row = NCOLS * N_U + k * N_O + n;
        nw = o_nw; nb = o_nb; ct = o_ct; col = o_col; te = temb + CDIM;
        nump = onum; catp = ocat;
    }
    float4 v;
    if (k < 3) {
        float x = nump[n * 3 + k];
        float4 w = *(const float4*)&nw[k * CDIM + c4];
        float4 bb = *(const float4*)&nb[k * CDIM + c4];
        float z0 = x * w.x + bb.x, z1 = x * w.y + bb.y;
        float z2 = x * w.z + bb.z, z3 = x * w.w + bb.w;
        v.x = z0 / (1.0f + __expf(-z0));
        v.y = z1 / (1.0f + __expf(-z1));
        v.z = z2 / (1.0f + __expf(-z2));
        v.w = z3 / (1.0f + __expf(-z3));
    } else {
        int idx = catp[n * 3 + (k - 3)];
        v = *(const float4*)&ct[((k - 3) * VOCAB + idx) * CDIM + c4];
    }
    float4 cv = *(const float4*)&col[k * CDIM + c4];
    float4 tv = *(const float4*)&te[c4];
    v.x += cv.x + tv.x; v.y += cv.y + tv.y;
    v.z += cv.z + tv.z; v.w += cv.w + tv.w;
    *(float4*)&out[(size_t)row * CDIM + c4] = v;
}

// ---------------- cp.async double-buffered bf16 HMMA text GEMM ----------------
#define U_TILES 157
#define O_TILES 79
#define NTILES  (U_TILES + O_TILES)
#define BK      32
#define ROWB    80
#define TILEB   (128 * ROWB)          // 10240
#define STAGEB  (4 * TILEB)           // 40960
#define SM_BIAS (2 * STAGEB)          // 81920
#define SM_TOT  (SM_BIAS + 512)
#define KCH     (TXTD / BK)           // 48

__global__ void __launch_bounds__(256, 2) txt_gemm_mma(
    const float* __restrict__ u_tb, const float* __restrict__ u_col,
    const float* __restrict__ o_tb, const float* __restrict__ o_col,
    const float* __restrict__ temb, float* __restrict__ out)
{
    extern __shared__ char smem[];
    uint32_t sb = smem_u32(smem);

    int tid = threadIdx.x;
    int lane = tid & 31;
    int wid = tid >> 5;
    int warp_m = wid & 3;
    int warp_n = wid >> 2;

    int tile = blockIdx.x;
    int half = blockIdx.y;

    int M, m0, orow0, wrow0, a_row0;
    const float *tb, *col, *te;
    if (tile < U_TILES) {
        M = N_U; m0 = tile * 128; orow0 = 6 * N_U; wrow0 = 0; a_row0 = m0;
        tb = u_tb; col = u_col; te = temb;
    } else {
        M = N_O; m0 = (tile - U_TILES) * 128;
        orow0 = NCOLS * N_U + 6 * N_O; wrow0 = CDIM; a_row0 = N_U + m0;
        tb = o_tb; col = o_col; te = temb + CDIM;
    }
    int ncol0 = half * 128;
    int brow0 = wrow0 + ncol0;

    float* s_bias = (float*)(smem + SM_BIAS);
    if (tid < 128) {
        int c = ncol0 + tid;
        s_bias[tid] = tb[c] + col[6 * CDIM + c] + te[c];
    }

    float acc[2][8][4];
    #pragma unroll
    for (int mi = 0; mi < 2; mi++)
        #pragma unroll
        for (int nt = 0; nt < 8; nt++)
            #pragma unroll
            for (int q = 0; q < 4; q++) acc[mi][nt][q] = 0.0f;

    // per-thread load coordinates (two groups)
    int r0 = tid >> 2,           cs0 = tid & 3;
    int r1 = (tid + 256) >> 2,   cs1 = (tid + 256) & 3;
    int arow0i = a_row0 + r0,    arow1i = a_row0 + r1;
    int apred0 = (arow0i < N_TOT) ? 16 : 0;
    int apred1 = (arow1i < N_TOT) ? 16 : 0;
    size_t aoff0 = (size_t)arow0i * TXTD + cs0 * 8;
    size_t aoff1 = (size_t)arow1i * TXTD + cs1 * 8;
    size_t boff0 = (size_t)(brow0 + r0) * TXTD + cs0 * 8;
    size_t boff1 = (size_t)(brow0 + r1) * TXTD + cs1 * 8;
    uint32_t d0 = (uint32_t)(r0 * ROWB + cs0 * 16);
    uint32_t d1 = (uint32_t)(r1 * ROWB + cs1 * 16);

    auto load_chunk = [&](int s, int ch) {
        int k0 = ch * BK;
        uint32_t base = sb + s * STAGEB;
        cp16(base + d0,             &g_a_hi[aoff0 + k0], apred0);
        cp16(base + d1,             &g_a_hi[aoff1 + k0], apred1);
        cp16(base + TILEB + d0,     &g_a_lo[aoff0 + k0], apred0);
        cp16(base + TILEB + d1,     &g_a_lo[aoff1 + k0], apred1);
        cp16(base + 2 * TILEB + d0, &g_w_hi[boff0 + k0], 16);
        cp16(base + 2 * TILEB + d1, &g_w_hi[boff1 + k0], 16);
        cp16(base + 3 * TILEB + d0, &g_w_lo[boff0 + k0], 16);
        cp16(base + 3 * TILEB + d1, &g_w_lo[boff1 + k0], 16);
        CP_COMMIT();
    };

    // ldmatrix lane-invariant offsets
    uint32_t a_row = (uint32_t)(warp_m * 32 + (lane & 15));
    uint32_t a_ch  = (uint32_t)(lane >> 4);
    uint32_t b_row = (uint32_t)(warp_n * 64 + (lane & 7) + ((lane >> 4) << 3));
    uint32_t b_ch  = (uint32_t)((lane >> 3) & 1);

    load_chunk(0, 0);

    for (int ch = 0; ch < KCH; ch++) {
        int s = ch & 1;
        if (ch + 1 < KCH) { load_chunk(s ^ 1, ch + 1); CP_WAIT1(); }
        else              { CP_WAIT0(); }
        __syncthreads();

        uint32_t sa_hi = sb + s * STAGEB;
        uint32_t sa_lo = sa_hi + TILEB;
        uint32_t sb_hi = sa_hi + 2 * TILEB;
        uint32_t sb_lo = sa_hi + 3 * TILEB;

        #pragma unroll
        for (int ks = 0; ks < 2; ks++) {
            uint32_t a_off = a_row * ROWB + (2 * ks + a_ch) * 16;
            uint32_t b_off = b_row * ROWB + (2 * ks + b_ch) * 16;

            uint32_t ah[2][4], bh[4][4];
            #pragma unroll
            for (int mi = 0; mi < 2; mi++)
                LDSM_X4(ah[mi][0], ah[mi][1], ah[mi][2], ah[mi][3],
                        sa_hi + a_off + mi * 16 * ROWB);
            #pragma unroll
            for (int np = 0; np < 4; np++)
                LDSM_X4(bh[np][0], bh[np][1], bh[np][2], bh[np][3],
                        sb_hi + b_off + np * 16 * ROWB);
            #pragma unroll
            for (int mi = 0; mi < 2; mi++)
                #pragma unroll
                for (int np = 0; np < 4; np++) {
                    MMA16816(acc[mi][2 * np],     ah[mi], bh[np][0], bh[np][1]);
                    MMA16816(acc[mi][2 * np + 1], ah[mi], bh[np][2], bh[np][3]);
                }

            uint32_t al[2][4];
            #pragma unroll
            for (int mi = 0; mi < 2; mi++)
                LDSM_X4(al[mi][0], al[mi][1], al[mi][2], al[mi][3],
                        sa_lo + a_off + mi * 16 * ROWB);
            #pragma unroll
            for (int mi = 0; mi < 2; mi++)
                #pragma unroll
                for (int np = 0; np < 4; np++) {
                    MMA16816(acc[mi][2 * np],     al[mi], bh[np][0], bh[np][1]);
                    MMA16816(acc[mi][2 * np + 1], al[mi], bh[np][2], bh[np][3]);
                }

            uint32_t bl[4][4];
            #pragma unroll
            for (int np = 0; np < 4; np++)
                LDSM_X4(bl[np][0], bl[np][1], bl[np][2], bl[np][3],
                        sb_lo + b_off + np * 16 * ROWB);
            #pragma unroll
            for (int mi = 0; mi < 2; mi++)
                #pragma unroll
                for (int np = 0; np < 4; np++) {
                    MMA16816(acc[mi][2 * np],     ah[mi], bl[np][0], bl[np][1]);
                    MMA16816(acc[mi][2 * np + 1], ah[mi], bl[np][2], bl[np][3]);
                }
        }
        __syncthreads();
    }

    // epilogue
    #pragma unroll
    for (int mi = 0; mi < 2; mi++) {
        #pragma unroll
        for (int rh = 0; rh < 2; rh++) {
            int row = m0 + warp_m * 32 + mi * 16 + (lane >> 2) + rh * 8;
            if (row >= M) continue;
            size_t rbase = (size_t)(orow0 + row) * CDIM + ncol0;
            #pragma unroll
            for (int nt = 0; nt < 8; nt++) {
                int cc = warp_n * 64 + nt * 8 + (lane & 3) * 2;
                float2 o;
                o.x = acc[mi][nt][rh * 2 + 0] + s_bias[cc];
                o.y = acc[mi][nt][rh * 2 + 1] + s_bias[cc + 1];
                *(float2*)&out[rbase + cc] = o;
            }
        }
    }
}

// ---------------- launch ----------------
extern "C" void kernel_launch(void* const* d_in, const int* in_sizes, int n_in,
                              void* d_out, int out_size) {
    const float* users_num   = (const float*)d_in[0];
    const int*   users_cat   = (const int*)  d_in[1];
    const float* users_text  = (const float*)d_in[2];
    const float* orders_num  = (const float*)d_in[3];
    const int*   orders_cat  = (const int*)  d_in[4];
    const float* orders_text = (const float*)d_in[5];
    const int*   edge_index  = (const int*)  d_in[6];
    const float* table_emb   = (const float*)d_in[7];
    const float* u_num_w     = (const float*)d_in[8];
    const float* u_num_b     = (const float*)d_in[9];
    const float* u_cat_tab   = (const float*)d_in[10];
    const float* u_txt_w     = (const float*)d_in[11];
    const float* u_txt_b     = (const float*)d_in[12];
    const float* u_col       = (const float*)d_in[13];
    const float* o_num_w     = (const float*)d_in[14];
    const float* o_num_b     = (const float*)d_in[15];
    const float* o_cat_tab   = (const float*)d_in[16];
    const float* o_txt_w     = (const float*)d_in[17];
    const float* o_txt_b     = (const float*)d_in[18];
    const float* o_col       = (const float*)d_in[19];

    float* out = (float*)d_out;

    cudaFuncSetAttribute(txt_gemm_mma, cudaFuncAttributeMaxDynamicSharedMemorySize, SM_TOT);

    // splits feeding the GEMM
    w_split_kernel<<<(CDIM * TXTD + 255) / 256, 256>>>(u_txt_w, o_txt_w);
    a_split_kernel<<<(N_TOT * TXTD / 4 + 255) / 256, 256>>>(users_text, orders_text);

    // edge table (scatter + sort)
    init_scratch_kernel<<<(NUM_NODES * MAXP + 255) / 256, 256>>>();
    edge_scatter_kernel<<<(E_EDGES + 255) / 256, 256>>>(edge_index);
    edge_sort_write_kernel<<<(N_O + 255) / 256, 256>>>(edge_index);

    // GEMM
    {
        dim3 grid(NTILES, 2);
        txt_gemm_mma<<<grid, 256, SM_TOT>>>(
            u_txt_b, u_col, o_txt_b, o_col, table_emb, out);
    }

    // gathers + indices + tokens
    f2p_gather_kernel<<<(X_ROWS * MAXP + 255) / 256, 256>>>(out);
    index_kernel<<<(3 * X_ROWS + 1 + 255) / 256, 256>>>(out);
    tok_kernel<<<(6 * N_U + 6 * N_O) / 4, 256>>>(
        users_num, users_cat, orders_num, orders_cat,
        u_num_w, u_num_b, u_cat_tab, u_col,
        o_num_w, o_num_b, o_cat_tab, o_col,
        table_emb, out);
}

// round 5
// speedup vs baseline: 3.0232x; 1.1738x over previous
#include <cuda_runtime.h>
#include <cuda_bf16.h>
#include <cstdint>

// ---------------- problem constants ----------------
#define N_U      20000
#define N_O      10000
#define N_TOT    30000
#define CDIM     256
#define TXTD     1536
#define NCOLS    7
#define E_EDGES  10000
#define MAXP     16
#define NUM_NODES 30000
#define VOCAB    101

#define X_ROWS   210000
#define OFF_NODE 53760000
#define OFF_COL  53970000
#define OFF_TAB  54180000
#define OFF_F2P  54390000
#define OFF_NN   57750000

// ---------------- device scratch ----------------
__device__ int g_tbl[NUM_NODES * MAXP];
__device__ int g_cnt[N_O];
__device__ int g_slot[N_O * 32];
__device__ __nv_bfloat16 g_w_hi[2 * CDIM * TXTD];
__device__ __nv_bfloat16 g_w_lo[2 * CDIM * TXTD];
__device__ __nv_bfloat16 g_a_hi[(size_t)N_TOT * TXTD];
__device__ __nv_bfloat16 g_a_lo[(size_t)N_TOT * TXTD];

// ---------------- helpers ----------------
__device__ __forceinline__ uint32_t smem_u32(const void* p) {
    uint32_t a;
    asm("{ .reg .u64 t; cvta.to.shared.u64 t, %1; cvt.u32.u64 %0, t; }" : "=r"(a) : "l"(p));
    return a;
}

__device__ __forceinline__ void split2(float a, float b, uint32_t& h, uint32_t& l) {
    __nv_bfloat162 hb = __floats2bfloat162_rn(a, b);
    float fa = __bfloat162float(hb.x);
    float fb = __bfloat162float(hb.y);
    __nv_bfloat162 lb = __floats2bfloat162_rn(a - fa, b - fb);
    h = *reinterpret_cast<uint32_t*>(&hb);
    l = *reinterpret_cast<uint32_t*>(&lb);
}

#define LDSM_X4(r0, r1, r2, r3, addr) \
    asm volatile("ldmatrix.sync.aligned.m8n8.x4.shared.b16 {%0,%1,%2,%3}, [%4];" \
        : "=r"(r0), "=r"(r1), "=r"(r2), "=r"(r3) : "r"(addr))

#define MMA16816(d, a, b0, b1) \
    asm volatile("mma.sync.aligned.m16n8k16.row.col.f32.bf16.bf16.f32 " \
        "{%0,%1,%2,%3}, {%4,%5,%6,%7}, {%8,%9}, {%0,%1,%2,%3};" \
        : "+f"((d)[0]), "+f"((d)[1]), "+f"((d)[2]), "+f"((d)[3]) \
        : "r"((a)[0]), "r"((a)[1]), "r"((a)[2]), "r"((a)[3]), "r"(b0), "r"(b1))

__device__ __forceinline__ void cp16(uint32_t dst, const void* src, int pred_sz) {
    asm volatile("cp.async.cg.shared.global [%0], [%1], 16, %2;"
                 :: "r"(dst), "l"(src), "r"(pred_sz));
}
#define CP_COMMIT() asm volatile("cp.async.commit_group;" ::: "memory")
#define CP_WAIT1()  asm volatile("cp.async.wait_group 1;" ::: "memory")
#define CP_WAIT0()  asm volatile("cp.async.wait_group 0;" ::: "memory")

// ---------------- init scratch ----------------
__global__ void init_scratch_kernel() {
    int i = blockIdx.x * blockDim.x + threadIdx.x;
    if (i < NUM_NODES * MAXP) g_tbl[i] = -1;
    if (i < N_O) g_cnt[i] = 0;
}

// ---------------- W split ----------------
__global__ void w_split_kernel(const float* __restrict__ uw, const float* __restrict__ ow) {
    int i = blockIdx.x * blockDim.x + threadIdx.x;
    if (i >= CDIM * TXTD) return;
    int idx = i * 2;
    float a, b;
    if (idx < CDIM * TXTD) { a = uw[idx]; b = uw[idx + 1]; }
    else { a = ow[idx - CDIM * TXTD]; b = ow[idx - CDIM * TXTD + 1]; }
    uint32_t h, l;
    split2(a, b, h, l);
    *(uint32_t*)&g_w_hi[idx] = h;
    *(uint32_t*)&g_w_lo[idx] = l;
}

// ---------------- A split ----------------
#define U_ELE (N_U * TXTD)
__global__ void a_split_kernel(const float* __restrict__ u, const float* __restrict__ o) {
    size_t i4 = ((size_t)blockIdx.x * blockDim.x + threadIdx.x) * 4;
    if (i4 >= (size_t)N_TOT * TXTD) return;
    const float* src = (i4 < U_ELE) ? (u + i4) : (o + (i4 - U_ELE));
    float4 v = *(const float4*)src;
    uint2 h, l;
    split2(v.x, v.y, h.x, l.x);
    split2(v.z, v.w, h.y, l.y);
    *(uint2*)&g_a_hi[i4] = h;
    *(uint2*)&g_a_lo[i4] = l;
}

// ---------------- edges: scatter + per-child sort ----------------
__global__ void edge_scatter_kernel(const int* __restrict__ edge_index) {
    int i = blockIdx.x * blockDim.x + threadIdx.x;
    if (i >= E_EDGES) return;
    int c = edge_index[i];
    int s = atomicAdd(&g_cnt[c], 1);
    if (s < 32) g_slot[c * 32 + s] = i;
}

__global__ void edge_sort_write_kernel(const int* __restrict__ edge_index) {
    int c = blockIdx.x * blockDim.x + threadIdx.x;
    if (c >= N_O) return;
    int n = g_cnt[c];
    if (n > 32) n = 32;
    int idx[32];
    for (int j = 0; j < n; j++) {
        int v = g_slot[c * 32 + j];
        int pos = j;
        while (pos > 0 && idx[pos - 1] > v) { idx[pos] = idx[pos - 1]; pos--; }
        idx[pos] = v;
    }
    int lim = n < MAXP ? n : MAXP;
    for (int r = 0; r < lim; r++)
        g_tbl[(N_U + c) * MAXP + r] = edge_index[E_EDGES + idx[r]];
}

// ---------------- f2p gather ----------------
__global__ void f2p_gather_kernel(float* __restrict__ out) {
    int i = blockIdx.x * blockDim.x + threadIdx.x;
    if (i >= X_ROWS * MAXP) return;
    int row = i >> 4;
    int s = i & (MAXP - 1);
    int node;
    if (row < NCOLS * N_U) node = row % N_U;
    else                   node = N_U + (row - NCOLS * N_U) % N_O;
    out[OFF_F2P + i] = (float)g_tbl[node * MAXP + s];
}

// ---------------- index arrays + num_nodes ----------------
__global__ void index_kernel(float* __restrict__ out) {
    int i = blockIdx.x * blockDim.x + threadIdx.x;
    if (i > 3 * X_ROWS) return;
    if (i == 3 * X_ROWS) { out[OFF_NN] = (float)NUM_NODES; return; }
    int r = i / X_ROWS;
    int j = i - r * X_ROWS;
    int node, colv, tabv;
    if (j < NCOLS * N_U) {
        node = j % N_U; colv = j / N_U; tabv = 0;
    } else {
        int jj = j - NCOLS * N_U;
        node = N_U + jj % N_O; colv = NCOLS + jj / N_O; tabv = 1;
    }
    if      (r == 0) out[OFF_NODE + j] = (float)node;
    else if (r == 1) out[OFF_COL  + j] = (float)colv;
    else             out[OFF_TAB  + j] = (float)tabv;
}

// ---------------- num + cat tokens ----------------
__global__ void tok_kernel(
    const float* __restrict__ unum, const int* __restrict__ ucat,
    const float* __restrict__ onum, const int* __restrict__ ocat,
    const float* __restrict__ u_nw, const float* __restrict__ u_nb,
    const float* __restrict__ u_ct, const float* __restrict__ u_col,
    const float* __restrict__ o_nw, const float* __restrict__ o_nb,
    const float* __restrict__ o_ct, const float* __restrict__ o_col,
    const float* __restrict__ temb, float* __restrict__ out)
{
    int rid = blockIdx.x * 4 + (threadIdx.x >> 6);
    int c4 = (threadIdx.x & 63) * 4;
    int k, n, row;
    const float *nw, *nb, *ct, *col, *te, *nump;
    const int* catp;
    if (rid < 6 * N_U) {
        k = rid / N_U; n = rid - k * N_U;
        row = k * N_U + n;
        nw = u_nw; nb = u_nb; ct = u_ct; col = u_col; te = temb;
        nump = unum; catp = ucat;
    } else {
        int b = rid - 6 * N_U;
        k = b / N_O; n = b - k * N_O;
        row = NCOLS * N_U + k * N_O + n;
        nw = o_nw; nb = o_nb; ct = o_ct; col = o_col; te = temb + CDIM;
        nump = onum; catp = ocat;
    }
    float4 v;
    if (k < 3) {
        float x = nump[n * 3 + k];
        float4 w = *(const float4*)&nw[k * CDIM + c4];
        float4 bb = *(const float4*)&nb[k * CDIM + c4];
        float z0 = x * w.x + bb.x, z1 = x * w.y + bb.y;
        float z2 = x * w.z + bb.z, z3 = x * w.w + bb.w;
        v.x = z0 / (1.0f + __expf(-z0));
        v.y = z1 / (1.0f + __expf(-z1));
        v.z = z2 / (1.0f + __expf(-z2));
        v.w = z3 / (1.0f + __expf(-z3));
    } else {
        int idx = catp[n * 3 + (k - 3)];
        v = *(const float4*)&ct[((k - 3) * VOCAB + idx) * CDIM + c4];
    }
    float4 cv = *(const float4*)&col[k * CDIM + c4];
    float4 tv = *(const float4*)&te[c4];
    v.x += cv.x + tv.x; v.y += cv.y + tv.y;
    v.z += cv.z + tv.z; v.w += cv.w + tv.w;
    *(float4*)&out[(size_t)row * CDIM + c4] = v;
}

// ---------------- persistent cp.async double-buffered bf16 HMMA text GEMM ----------------
#define U_TILES 157
#define O_TILES 79
#define NTILES  (U_TILES + O_TILES)
#define NWORK   (NTILES * 2)
#define GEMM_GRID 296
#define BK      32
#define ROWB    80
#define TILEB   (128 * ROWB)
#define STAGEB  (4 * TILEB)
#define SM_BIAS (2 * STAGEB)
#define SM_TOT  (SM_BIAS + 512)
#define KCH     (TXTD / BK)

__global__ void __launch_bounds__(256, 2) txt_gemm_mma(
    const float* __restrict__ u_tb, const float* __restrict__ u_col,
    const float* __restrict__ o_tb, const float* __restrict__ o_col,
    const float* __restrict__ temb, float* __restrict__ out)
{
    extern __shared__ char smem[];
    uint32_t sb = smem_u32(smem);

    int tid = threadIdx.x;
    int lane = tid & 31;
    int wid = tid >> 5;
    int warp_m = wid & 3;
    int warp_n = wid >> 2;

    // per-thread load geometry (work-independent)
    int r0 = tid >> 2,         cs0 = tid & 3;
    int r1 = (tid + 256) >> 2, cs1 = (tid + 256) & 3;
    uint32_t d0 = (uint32_t)(r0 * ROWB + cs0 * 16);
    uint32_t d1 = (uint32_t)(r1 * ROWB + cs1 * 16);

    // ldmatrix lane-invariant offsets
    uint32_t a_row = (uint32_t)(warp_m * 32 + (lane & 15));
    uint32_t a_ch  = (uint32_t)(lane >> 4);
    uint32_t b_row = (uint32_t)(warp_n * 64 + (lane & 7) + ((lane >> 4) << 3));
    uint32_t b_ch  = (uint32_t)((lane >> 3) & 1);

    float* s_bias = (float*)(smem + SM_BIAS);

    for (int work = blockIdx.x; work < NWORK; work += GEMM_GRID) {
        int tile = work >> 1;
        int half = work & 1;

        int M, m0, orow0, wrow0, a_row0;
        const float *tb, *col, *te;
        if (tile < U_TILES) {
            M = N_U; m0 = tile * 128; orow0 = 6 * N_U; wrow0 = 0; a_row0 = m0;
            tb = u_tb; col = u_col; te = temb;
        } else {
            M = N_O; m0 = (tile - U_TILES) * 128;
            orow0 = NCOLS * N_U + 6 * N_O; wrow0 = CDIM; a_row0 = N_U + m0;
            tb = o_tb; col = o_col; te = temb + CDIM;
        }
        int ncol0 = half * 128;
        int brow0 = wrow0 + ncol0;

        if (tid < 128) {
            int c = ncol0 + tid;
            s_bias[tid] = tb[c] + col[6 * CDIM + c] + te[c];
        }

        float acc[2][8][4];
        #pragma unroll
        for (int mi = 0; mi < 2; mi++)
            #pragma unroll
            for (int nt = 0; nt < 8; nt++)
                #pragma unroll
                for (int q = 0; q < 4; q++) acc[mi][nt][q] = 0.0f;

        int arow0i = a_row0 + r0, arow1i = a_row0 + r1;
        int apred0 = (arow0i < N_TOT) ? 16 : 0;
        int apred1 = (arow1i < N_TOT) ? 16 : 0;
        size_t aoff0 = (size_t)arow0i * TXTD + cs0 * 8;
        size_t aoff1 = (size_t)arow1i * TXTD + cs1 * 8;
        size_t boff0 = (size_t)(brow0 + r0) * TXTD + cs0 * 8;
        size_t boff1 = (size_t)(brow0 + r1) * TXTD + cs1 * 8;

        auto load_chunk = [&](int s, int ch) {
            int k0 = ch * BK;
            uint32_t base = sb + s * STAGEB;
            cp16(base + d0,             &g_a_hi[aoff0 + k0], apred0);
            cp16(base + d1,             &g_a_hi[aoff1 + k0], apred1);
            cp16(base + TILEB + d0,     &g_a_lo[aoff0 + k0], apred0);
            cp16(base + TILEB + d1,     &g_a_lo[aoff1 + k0], apred1);
            cp16(base + 2 * TILEB + d0, &g_w_hi[boff0 + k0], 16);
            cp16(base + 2 * TILEB + d1, &g_w_hi[boff1 + k0], 16);
            cp16(base + 3 * TILEB + d0, &g_w_lo[boff0 + k0], 16);
            cp16(base + 3 * TILEB + d1, &g_w_lo[boff1 + k0], 16);
            CP_COMMIT();
        };

        load_chunk(0, 0);

        for (int ch = 0; ch < KCH; ch++) {
            int s = ch & 1;
            if (ch + 1 < KCH) { load_chunk(s ^ 1, ch + 1); CP_WAIT1(); }
            else              { CP_WAIT0(); }
            __syncthreads();

            uint32_t sa_hi = sb + s * STAGEB;
            uint32_t sa_lo = sa_hi + TILEB;
            uint32_t sb_hi = sa_hi + 2 * TILEB;
            uint32_t sb_lo = sa_hi + 3 * TILEB;

            #pragma unroll
            for (int ks = 0; ks < 2; ks++) {
                uint32_t a_off = a_row * ROWB + (2 * ks + a_ch) * 16;
                uint32_t b_off = b_row * ROWB + (2 * ks + b_ch) * 16;

                uint32_t ah[2][4], bh[4][4];
                #pragma unroll
                for (int mi = 0; mi < 2; mi++)
                    LDSM_X4(ah[mi][0], ah[mi][1], ah[mi][2], ah[mi][3],
                            sa_hi + a_off + mi * 16 * ROWB);
                #pragma unroll
                for (int np = 0; np < 4; np++)
                    LDSM_X4(bh[np][0], bh[np][1], bh[np][2], bh[np][3],
                            sb_hi + b_off + np * 16 * ROWB);
                #pragma unroll
                for (int mi = 0; mi < 2; mi++)
                    #pragma unroll
                    for (int np = 0; np < 4; np++) {
                        MMA16816(acc[mi][2 * np],     ah[mi], bh[np][0], bh[np][1]);
                        MMA16816(acc[mi][2 * np + 1], ah[mi], bh[np][2], bh[np][3]);
                    }

                uint32_t al[2][4];
                #pragma unroll
                for (int mi = 0; mi < 2; mi++)
                    LDSM_X4(al[mi][0], al[mi][1], al[mi][2], al[mi][3],
                            sa_lo + a_off + mi * 16 * ROWB);
                #pragma unroll
                for (int mi = 0; mi < 2; mi++)
                    #pragma unroll
                    for (int np = 0; np < 4; np++) {
                        MMA16816(acc[mi][2 * np],     al[mi], bh[np][0], bh[np][1]);
                        MMA16816(acc[mi][2 * np + 1], al[mi], bh[np][2], bh[np][3]);
                    }

                uint32_t bl[4][4];
                #pragma unroll
                for (int np = 0; np < 4; np++)
                    LDSM_X4(bl[np][0], bl[np][1], bl[np][2], bl[np][3],
                            sb_lo + b_off + np * 16 * ROWB);
                #pragma unroll
                for (int mi = 0; mi < 2; mi++)
                    #pragma unroll
                    for (int np = 0; np < 4; np++) {
                        MMA16816(acc[mi][2 * np],     ah[mi], bl[np][0], bl[np][1]);
                        MMA16816(acc[mi][2 * np + 1], ah[mi], bl[np][2], bl[np][3]);
                    }
            }
            __syncthreads();
        }

        // epilogue
        #pragma unroll
        for (int mi = 0; mi < 2; mi++) {
            #pragma unroll
            for (int rh = 0; rh < 2; rh++) {
                int row = m0 + warp_m * 32 + mi * 16 + (lane >> 2) + rh * 8;
                if (row >= M) continue;
                size_t rbase = (size_t)(orow0 + row) * CDIM + ncol0;
                #pragma unroll
                for (int nt = 0; nt < 8; nt++) {
                    int cc = warp_n * 64 + nt * 8 + (lane & 3) * 2;
                    float2 o;
                    o.x = acc[mi][nt][rh * 2 + 0] + s_bias[cc];
                    o.y = acc[mi][nt][rh * 2 + 1] + s_bias[cc + 1];
                    *(float2*)&out[rbase + cc] = o;
                }
            }
        }
        __syncthreads();   // protect s_bias before next work item rewrites it
    }
}

// ---------------- launch ----------------
extern "C" void kernel_launch(void* const* d_in, const int* in_sizes, int n_in,
                              void* d_out, int out_size) {
    const float* users_num   = (const float*)d_in[0];
    const int*   users_cat   = (const int*)  d_in[1];
    const float* users_text  = (const float*)d_in[2];
    const float* orders_num  = (const float*)d_in[3];
    const int*   orders_cat  = (const int*)  d_in[4];
    const float* orders_text = (const float*)d_in[5];
    const int*   edge_index  = (const int*)  d_in[6];
    const float* table_emb   = (const float*)d_in[7];
    const float* u_num_w     = (const float*)d_in[8];
    const float* u_num_b     = (const float*)d_in[9];
    const float* u_cat_tab   = (const float*)d_in[10];
    const float* u_txt_w     = (const float*)d_in[11];
    const float* u_txt_b     = (const float*)d_in[12];
    const float* u_col       = (const float*)d_in[13];
    const float* o_num_w     = (const float*)d_in[14];
    const float* o_num_b     = (const float*)d_in[15];
    const float* o_cat_tab   = (const float*)d_in[16];
    const float* o_txt_w     = (const float*)d_in[17];
    const float* o_txt_b     = (const float*)d_in[18];
    const float* o_col       = (const float*)d_in[19];

    float* out = (float*)d_out;

    // one-time host-side setup (no device allocations)
    static cudaStream_t s2 = nullptr;
    static cudaEvent_t evFork = nullptr, evJoin = nullptr;
    static bool setup_done = false;
    if (!setup_done) {
        cudaFuncSetAttribute(txt_gemm_mma, cudaFuncAttributeMaxDynamicSharedMemorySize, SM_TOT);
        if (cudaStreamCreateWithFlags(&s2, cudaStreamNonBlocking) != cudaSuccess) s2 = nullptr;
        if (s2) {
            cudaEventCreateWithFlags(&evFork, cudaEventDisableTiming);
            cudaEventCreateWithFlags(&evJoin, cudaEventDisableTiming);
        }
        setup_done = true;
    }

    cudaStream_t side = s2 ? s2 : (cudaStream_t)0;
    if (s2) {
        cudaEventRecord(evFork, 0);
        cudaStreamWaitEvent(s2, evFork, 0);
    }

    // ---- side branch: edge table, gathers, indices, tokens ----
    init_scratch_kernel<<<(NUM_NODES * MAXP + 255) / 256, 256, 0, side>>>();
    edge_scatter_kernel<<<(E_EDGES + 255) / 256, 256, 0, side>>>(edge_index);
    edge_sort_write_kernel<<<(N_O + 255) / 256, 256, 0, side>>>(edge_index);
    f2p_gather_kernel<<<(X_ROWS * MAXP + 255) / 256, 256, 0, side>>>(out);
    index_kernel<<<(3 * X_ROWS + 1 + 255) / 256, 256, 0, side>>>(out);
    tok_kernel<<<(6 * N_U + 6 * N_O) / 4, 256, 0, side>>>(
        users_num, users_cat, orders_num, orders_cat,
        u_num_w, u_num_b, u_cat_tab, u_col,
        o_num_w, o_num_b, o_cat_tab, o_col,
        table_emb, out);
    if (s2) cudaEventRecord(evJoin, s2);

    // ---- main branch: splits + GEMM ----
    w_split_kernel<<<(CDIM * TXTD + 255) / 256, 256>>>(u_txt_w, o_txt_w);
    a_split_kernel<<<(N_TOT * TXTD / 4 + 255) / 256, 256>>>(users_text, orders_text);
    txt_gemm_mma<<<GEMM_GRID, 256, SM_TOT>>>(
        u_txt_b, u_col, o_txt_b, o_col, table_emb, out);

    if (s2) cudaStreamWaitEvent(0, evJoin, 0);
}

// round 6
// speedup vs baseline: 3.7154x; 1.2290x over previous
#include <cuda_runtime.h>
#include <cuda_bf16.h>
#include <cstdint>

// ---------------- problem constants ----------------
#define N_U      20000
#define N_O      10000
#define N_TOT    30000
#define CDIM     256
#define TXTD     1536
#define NCOLS    7
#define E_EDGES  10000
#define MAXP     16
#define NUM_NODES 30000
#define VOCAB    101

#define X_ROWS   210000
#define OFF_NODE 53760000
#define OFF_COL  53970000
#define OFF_TAB  54180000
#define OFF_F2P  54390000
#define OFF_NN   57750000

// ---------------- device scratch ----------------
__device__ int g_tbl[NUM_NODES * MAXP];
__device__ int g_cnt[N_O];
__device__ int g_slot[N_O * 32];
__device__ __nv_bfloat16 g_w_hi[2 * CDIM * TXTD];
__device__ __nv_bfloat16 g_w_lo[2 * CDIM * TXTD];

// ---------------- helpers ----------------
__device__ __forceinline__ uint32_t smem_u32(const void* p) {
    uint32_t a;
    asm("{ .reg .u64 t; cvta.to.shared.u64 t, %1; cvt.u32.u64 %0, t; }" : "=r"(a) : "l"(p));
    return a;
}

__device__ __forceinline__ void split2(float a, float b, uint32_t& h, uint32_t& l) {
    __nv_bfloat162 hb = __floats2bfloat162_rn(a, b);
    float fa = __bfloat162float(hb.x);
    float fb = __bfloat162float(hb.y);
    __nv_bfloat162 lb = __floats2bfloat162_rn(a - fa, b - fb);
    h = *reinterpret_cast<uint32_t*>(&hb);
    l = *reinterpret_cast<uint32_t*>(&lb);
}

#define LDSM_X4(r0, r1, r2, r3, addr) \
    asm volatile("ldmatrix.sync.aligned.m8n8.x4.shared.b16 {%0,%1,%2,%3}, [%4];" \
        : "=r"(r0), "=r"(r1), "=r"(r2), "=r"(r3) : "r"(addr))

#define MMA16816(d, a, b0, b1) \
    asm volatile("mma.sync.aligned.m16n8k16.row.col.f32.bf16.bf16.f32 " \
        "{%0,%1,%2,%3}, {%4,%5,%6,%7}, {%8,%9}, {%0,%1,%2,%3};" \
        : "+f"((d)[0]), "+f"((d)[1]), "+f"((d)[2]), "+f"((d)[3]) \
        : "r"((a)[0]), "r"((a)[1]), "r"((a)[2]), "r"((a)[3]), "r"(b0), "r"(b1))

__device__ __forceinline__ void cp16(uint32_t dst, const void* src, int pred_sz) {
    asm volatile("cp.async.cg.shared.global [%0], [%1], 16, %2;"
                 :: "r"(dst), "l"(src), "r"(pred_sz));
}
#define CP_COMMIT() asm volatile("cp.async.commit_group;" ::: "memory")
#define CP_WAIT1()  asm volatile("cp.async.wait_group 1;" ::: "memory")
#define CP_WAIT0()  asm volatile("cp.async.wait_group 0;" ::: "memory")

// ---------------- init scratch ----------------
__global__ void init_scratch_kernel() {
    int i = blockIdx.x * blockDim.x + threadIdx.x;
    if (i < NUM_NODES * MAXP) g_tbl[i] = -1;
    if (i < N_O) g_cnt[i] = 0;
}

// ---------------- W split ----------------
__global__ void w_split_kernel(const float* __restrict__ uw, const float* __restrict__ ow) {
    int i = blockIdx.x * blockDim.x + threadIdx.x;
    if (i >= CDIM * TXTD) return;
    int idx = i * 2;
    float a, b;
    if (idx < CDIM * TXTD) { a = uw[idx]; b = uw[idx + 1]; }
    else { a = ow[idx - CDIM * TXTD]; b = ow[idx - CDIM * TXTD + 1]; }
    uint32_t h, l;
    split2(a, b, h, l);
    *(uint32_t*)&g_w_hi[idx] = h;
    *(uint32_t*)&g_w_lo[idx] = l;
}

// ---------------- edges: scatter + per-child sort ----------------
__global__ void edge_scatter_kernel(const int* __restrict__ edge_index) {
    int i = blockIdx.x * blockDim.x + threadIdx.x;
    if (i >= E_EDGES) return;
    int c = edge_index[i];
    int s = atomicAdd(&g_cnt[c], 1);
    if (s < 32) g_slot[c * 32 + s] = i;
}

__global__ void edge_sort_write_kernel(const int* __restrict__ edge_index) {
    int c = blockIdx.x * blockDim.x + threadIdx.x;
    if (c >= N_O) return;
    int n = g_cnt[c];
    if (n > 32) n = 32;
    int idx[32];
    for (int j = 0; j < n; j++) {
        int v = g_slot[c * 32 + j];
        int pos = j;
        while (pos > 0 && idx[pos - 1] > v) { idx[pos] = idx[pos - 1]; pos--; }
        idx[pos] = v;
    }
    int lim = n < MAXP ? n : MAXP;
    for (int r = 0; r < lim; r++)
        g_tbl[(N_U + c) * MAXP + r] = edge_index[E_EDGES + idx[r]];
}

// ---------------- f2p gather ----------------
__global__ void f2p_gather_kernel(float* __restrict__ out) {
    int i = blockIdx.x * blockDim.x + threadIdx.x;
    if (i >= X_ROWS * MAXP) return;
    int row = i >> 4;
    int s = i & (MAXP - 1);
    int node;
    if (row < NCOLS * N_U) node = row % N_U;
    else                   node = N_U + (row - NCOLS * N_U) % N_O;
    out[OFF_F2P + i] = (float)g_tbl[node * MAXP + s];
}

// ---------------- index arrays + num_nodes ----------------
__global__ void index_kernel(float* __restrict__ out) {
    int i = blockIdx.x * blockDim.x + threadIdx.x;
    if (i > 3 * X_ROWS) return;
    if (i == 3 * X_ROWS) { out[OFF_NN] = (float)NUM_NODES; return; }
    int r = i / X_ROWS;
    int j = i - r * X_ROWS;
    int node, colv, tabv;
    if (j < NCOLS * N_U) {
        node = j % N_U; colv = j / N_U; tabv = 0;
    } else {
        int jj = j - NCOLS * N_U;
        node = N_U + jj % N_O; colv = NCOLS + jj / N_O; tabv = 1;
    }
    if      (r == 0) out[OFF_NODE + j] = (float)node;
    else if (r == 1) out[OFF_COL  + j] = (float)colv;
    else             out[OFF_TAB  + j] = (float)tabv;
}

// ---------------- num + cat tokens ----------------
__global__ void tok_kernel(
    const float* __restrict__ unum, const int* __restrict__ ucat,
    const float* __restrict__ onum, const int* __restrict__ ocat,
    const float* __restrict__ u_nw, const float* __restrict__ u_nb,
    const float* __restrict__ u_ct, const float* __restrict__ u_col,
    const float* __restrict__ o_nw, const float* __restrict__ o_nb,
    const float* __restrict__ o_ct, const float* __restrict__ o_col,
    const float* __restrict__ temb, float* __restrict__ out)
{
    int rid = blockIdx.x * 4 + (threadIdx.x >> 6);
    int c4 = (threadIdx.x & 63) * 4;
    int k, n, row;
    const float *nw, *nb, *ct, *col, *te, *nump;
    const int* catp;
    if (rid < 6 * N_U) {
        k = rid / N_U; n = rid - k * N_U;
        row = k * N_U + n;
        nw = u_nw; nb = u_nb; ct = u_ct; col = u_col; te = temb;
        nump = unum; catp = ucat;
    } else {
        int b = rid - 6 * N_U;
        k = b / N_O; n = b - k * N_O;
        row = NCOLS * N_U + k * N_O + n;
        nw = o_nw; nb = o_nb; ct = o_ct; col = o_col; te = temb + CDIM;
        nump = onum; catp = ocat;
    }
    float4 v;
    if (k < 3) {
        float x = nump[n * 3 + k];
        float4 w = *(const float4*)&nw[k * CDIM + c4];
        float4 bb = *(const float4*)&nb[k * CDIM + c4];
        float z0 = x * w.x + bb.x, z1 = x * w.y + bb.y;
        float z2 = x * w.z + bb.z, z3 = x * w.w + bb.w;
        v.x = z0 / (1.0f + __expf(-z0));
        v.y = z1 / (1.0f + __expf(-z1));
        v.z = z2 / (1.0f + __expf(-z2));
        v.w = z3 / (1.0f + __expf(-z3));
    } else {
        int idx = catp[n * 3 + (k - 3)];
        v = *(const float4*)&ct[((k - 3) * VOCAB + idx) * CDIM + c4];
    }
    float4 cv = *(const float4*)&col[k * CDIM + c4];
    float4 tv = *(const float4*)&te[c4];
    v.x += cv.x + tv.x; v.y += cv.y + tv.y;
    v.z += cv.z + tv.z; v.w += cv.w + tv.w;
    *(float4*)&out[(size_t)row * CDIM + c4] = v;
}

// ---------------- persistent fused-split bf16 HMMA text GEMM ----------------
// A loaded fp32 with register prefetch, split to bf16 hi/lo in-kernel.
// B streamed via cp.async from pre-split g_w_hi/g_w_lo.
#define U_TILES 157
#define O_TILES 79
#define NTILES  (U_TILES + O_TILES)
#define NWORK   (NTILES * 2)
#define GEMM_GRID 296
#define BK      32
#define ROWB    80
#define TILEB   (128 * ROWB)
#define STAGEB  (4 * TILEB)
#define SM_BIAS (2 * STAGEB)
#define SM_TOT  (SM_BIAS + 512)
#define KCH     (TXTD / BK)

__global__ void __launch_bounds__(256, 2) txt_gemm_mma(
    const float* __restrict__ uA, const float* __restrict__ oA,
    const float* __restrict__ u_tb, const float* __restrict__ u_col,
    const float* __restrict__ o_tb, const float* __restrict__ o_col,
    const float* __restrict__ temb, float* __restrict__ out)
{
    extern __shared__ char smem[];
    uint32_t sb = smem_u32(smem);

    int tid = threadIdx.x;
    int lane = tid & 31;
    int wid = tid >> 5;
    int warp_m = wid & 3;
    int warp_n = wid >> 2;

    // A load geometry: thread -> (row = tid>>1, 16 consecutive fp32 at (tid&1)*16)
    int a_r   = tid >> 1;
    int a_c16 = (tid & 1) * 16;
    uint32_t a_sts = (uint32_t)(a_r * ROWB + a_c16 * 2);   // byte offset in bf16 tile

    // B load geometry (two 16B groups per thread)
    int r0 = tid >> 2,         cs0 = tid & 3;
    int r1 = (tid + 256) >> 2, cs1 = (tid + 256) & 3;
    uint32_t d0 = (uint32_t)(r0 * ROWB + cs0 * 16);
    uint32_t d1 = (uint32_t)(r1 * ROWB + cs1 * 16);

    // ldmatrix lane-invariant offsets
    uint32_t a_row = (uint32_t)(warp_m * 32 + (lane & 15));
    uint32_t a_ch  = (uint32_t)(lane >> 4);
    uint32_t b_row = (uint32_t)(warp_n * 64 + (lane & 7) + ((lane >> 4) << 3));
    uint32_t b_ch  = (uint32_t)((lane >> 3) & 1);

    float* s_bias = (float*)(smem + SM_BIAS);

    for (int work = blockIdx.x; work < NWORK; work += GEMM_GRID) {
        int tile = work >> 1;
        int half = work & 1;

        const float* A;
        int M, m0, orow0, wrow0;
        const float *tb, *col, *te;
        if (tile < U_TILES) {
            A = uA; M = N_U; m0 = tile * 128; orow0 = 6 * N_U; wrow0 = 0;
            tb = u_tb; col = u_col; te = temb;
        } else {
            A = oA; M = N_O; m0 = (tile - U_TILES) * 128;
            orow0 = NCOLS * N_U + 6 * N_O; wrow0 = CDIM;
            tb = o_tb; col = o_col; te = temb + CDIM;
        }
        int ncol0 = half * 128;
        int brow0 = wrow0 + ncol0;

        if (tid < 128) {
            int c = ncol0 + tid;
            s_bias[tid] = tb[c] + col[6 * CDIM + c] + te[c];
        }

        float acc[2][8][4];
        #pragma unroll
        for (int mi = 0; mi < 2; mi++)
            #pragma unroll
            for (int nt = 0; nt < 8; nt++)
                #pragma unroll
                for (int q = 0; q < 4; q++) acc[mi][nt][q] = 0.0f;

        // A row pointer for this work item
        int a_gr = m0 + a_r;
        bool a_ok = (a_gr < M);
        const float* a_ptr = A + (size_t)(a_ok ? a_gr : 0) * TXTD + a_c16;

        size_t boff0 = (size_t)(brow0 + r0) * TXTD + cs0 * 8;
        size_t boff1 = (size_t)(brow0 + r1) * TXTD + cs1 * 8;

        auto load_B = [&](int s, int ch) {
            int k0 = ch * BK;
            uint32_t base = sb + s * STAGEB;
            cp16(base + 2 * TILEB + d0, &g_w_hi[boff0 + k0], 16);
            cp16(base + 2 * TILEB + d1, &g_w_hi[boff1 + k0], 16);
            cp16(base + 3 * TILEB + d0, &g_w_lo[boff0 + k0], 16);
            cp16(base + 3 * TILEB + d1, &g_w_lo[boff1 + k0], 16);
            CP_COMMIT();
        };

        // prefetch A chunk 0 + B chunk 0
        float4 av0, av1, av2, av3;
        {
            const float4* p = (const float4*)a_ptr;
            if (a_ok) { av0 = p[0]; av1 = p[1]; av2 = p[2]; av3 = p[3]; }
            else { av0 = av1 = av2 = av3 = make_float4(0.f, 0.f, 0.f, 0.f); }
        }
        load_B(0, 0);

        for (int ch = 0; ch < KCH; ch++) {
            int s = ch & 1;
            if (ch + 1 < KCH) { load_B(s ^ 1, ch + 1); CP_WAIT1(); }
            else              { CP_WAIT0(); }

            // convert prefetched A -> hi/lo SMEM (stage s)
            {
                uint32_t base = sb + s * STAGEB;
                uint4 h0, l0, h1, l1;
                split2(av0.x, av0.y, h0.x, l0.x);
                split2(av0.z, av0.w, h0.y, l0.y);
                split2(av1.x, av1.y, h0.z, l0.z);
                split2(av1.z, av1.w, h0.w, l0.w);
                split2(av2.x, av2.y, h1.x, l1.x);
                split2(av2.z, av2.w, h1.y, l1.y);
                split2(av3.x, av3.y, h1.z, l1.z);
                split2(av3.z, av3.w, h1.w, l1.w);
                asm volatile("st.shared.v4.b32 [%0], {%1,%2,%3,%4};" ::
                    "r"(base + a_sts), "r"(h0.x), "r"(h0.y), "r"(h0.z), "r"(h0.w));
                asm volatile("st.shared.v4.b32 [%0], {%1,%2,%3,%4};" ::
                    "r"(base + a_sts + 16), "r"(h1.x), "r"(h1.y), "r"(h1.z), "r"(h1.w));
                asm volatile("st.shared.v4.b32 [%0], {%1,%2,%3,%4};" ::
                    "r"(base + TILEB + a_sts), "r"(l0.x), "r"(l0.y), "r"(l0.z), "r"(l0.w));
                asm volatile("st.shared.v4.b32 [%0], {%1,%2,%3,%4};" ::
                    "r"(base + TILEB + a_sts + 16), "r"(l1.x), "r"(l1.y), "r"(l1.z), "r"(l1.w));
            }
            // prefetch A for next chunk (latency hidden behind MMA)
            if (ch + 1 < KCH) {
                const float4* p = (const float4*)(a_ptr + (ch + 1) * BK);
                if (a_ok) { av0 = p[0]; av1 = p[1]; av2 = p[2]; av3 = p[3]; }
            }
            __syncthreads();

            uint32_t sa_hi = sb + s * STAGEB;
            uint32_t sa_lo = sa_hi + TILEB;
            uint32_t sb_hi = sa_hi + 2 * TILEB;
            uint32_t sb_lo = sa_hi + 3 * TILEB;

            #pragma unroll
            for (int ks = 0; ks < 2; ks++) {
                uint32_t a_off = a_row * ROWB + (2 * ks + a_ch) * 16;
                uint32_t b_off = b_row * ROWB + (2 * ks + b_ch) * 16;

                uint32_t ah[2][4], bh[4][4];
                #pragma unroll
                for (int mi = 0; mi < 2; mi++)
                    LDSM_X4(ah[mi][0], ah[mi][1], ah[mi][2], ah[mi][3],
                            sa_hi + a_off + mi * 16 * ROWB);
                #pragma unroll
                for (int np = 0; np < 4; np++)
                    LDSM_X4(bh[np][0], bh[np][1], bh[np][2], bh[np][3],
                            sb_hi + b_off + np * 16 * ROWB);
                #pragma unroll
                for (int mi = 0; mi < 2; mi++)
                    #pragma unroll
                    for (int np = 0; np < 4; np++) {
                        MMA16816(acc[mi][2 * np],     ah[mi], bh[np][0], bh[np][1]);
                        MMA16816(acc[mi][2 * np + 1], ah[mi], bh[np][2], bh[np][3]);
                    }

                uint32_t al[2][4];
                #pragma unroll
                for (int mi = 0; mi < 2; mi++)
                    LDSM_X4(al[mi][0], al[mi][1], al[mi][2], al[mi][3],
                            sa_lo + a_off + mi * 16 * ROWB);
                #pragma unroll
                for (int mi = 0; mi < 2; mi++)
                    #pragma unroll
                    for (int np = 0; np < 4; np++) {
                        MMA16816(acc[mi][2 * np],     al[mi], bh[np][0], bh[np][1]);
                        MMA16816(acc[mi][2 * np + 1], al[mi], bh[np][2], bh[np][3]);
                    }

                uint32_t bl[4][4];
                #pragma unroll
                for (int np = 0; np < 4; np++)
                    LDSM_X4(bl[np][0], bl[np][1], bl[np][2], bl[np][3],
                            sb_lo + b_off + np * 16 * ROWB);
                #pragma unroll
                for (int mi = 0; mi < 2; mi++)
                    #pragma unroll
                    for (int np = 0; np < 4; np++) {
                        MMA16816(acc[mi][2 * np],     ah[mi], bl[np][0], bl[np][1]);
                        MMA16816(acc[mi][2 * np + 1], ah[mi], bl[np][2], bl[np][3]);
                    }
            }
            __syncthreads();
        }

        // epilogue
        #pragma unroll
        for (int mi = 0; mi < 2; mi++) {
            #pragma unroll
            for (int rh = 0; rh < 2; rh++) {
                int row = m0 + warp_m * 32 + mi * 16 + (lane >> 2) + rh * 8;
                if (row >= M) continue;
                size_t rbase = (size_t)(orow0 + row) * CDIM + ncol0;
                #pragma unroll
                for (int nt = 0; nt < 8; nt++) {
                    int cc = warp_n * 64 + nt * 8 + (lane & 3) * 2;
                    float2 o;
                    o.x = acc[mi][nt][rh * 2 + 0] + s_bias[cc];
                    o.y = acc[mi][nt][rh * 2 + 1] + s_bias[cc + 1];
                    *(float2*)&out[rbase + cc] = o;
                }
            }
        }
        __syncthreads();   // protect s_bias before next work item rewrites it
    }
}

// ---------------- launch ----------------
extern "C" void kernel_launch(void* const* d_in, const int* in_sizes, int n_in,
                              void* d_out, int out_size) {
    const float* users_num   = (const float*)d_in[0];
    const int*   users_cat   = (const int*)  d_in[1];
    const float* users_text  = (const float*)d_in[2];
    const float* orders_num  = (const float*)d_in[3];
    const int*   orders_cat  = (const int*)  d_in[4];
    const float* orders_text = (const float*)d_in[5];
    const int*   edge_index  = (const int*)  d_in[6];
    const float* table_emb   = (const float*)d_in[7];
    const float* u_num_w     = (const float*)d_in[8];
    const float* u_num_b     = (const float*)d_in[9];
    const float* u_cat_tab   = (const float*)d_in[10];
    const float* u_txt_w     = (const float*)d_in[11];
    const float* u_txt_b     = (const float*)d_in[12];
    const float* u_col       = (const float*)d_in[13];
    const float* o_num_w     = (const float*)d_in[14];
    const float* o_num_b     = (const float*)d_in[15];
    const float* o_cat_tab   = (const float*)d_in[16];
    const float* o_txt_w     = (const float*)d_in[17];
    const float* o_txt_b     = (const float*)d_in[18];
    const float* o_col       = (const float*)d_in[19];

    float* out = (float*)d_out;

    // one-time host-side setup (no device allocations)
    static cudaStream_t s2 = nullptr;
    static cudaEvent_t evFork = nullptr, evJoin = nullptr;
    static bool setup_done = false;
    if (!setup_done) {
        cudaFuncSetAttribute(txt_gemm_mma, cudaFuncAttributeMaxDynamicSharedMemorySize, SM_TOT);
        if (cudaStreamCreateWithFlags(&s2, cudaStreamNonBlocking) != cudaSuccess) s2 = nullptr;
        if (s2) {
            cudaEventCreateWithFlags(&evFork, cudaEventDisableTiming);
            cudaEventCreateWithFlags(&evJoin, cudaEventDisableTiming);
        }
        setup_done = true;
    }

    cudaStream_t side = s2 ? s2 : (cudaStream_t)0;
    if (s2) {
        cudaEventRecord(evFork, 0);
        cudaStreamWaitEvent(s2, evFork, 0);
    }

    // ---- side branch: edge table, gathers, indices, tokens ----
    init_scratch_kernel<<<(NUM_NODES * MAXP + 255) / 256, 256, 0, side>>>();
    edge_scatter_kernel<<<(E_EDGES + 255) / 256, 256, 0, side>>>(edge_index);
    edge_sort_write_kernel<<<(N_O + 255) / 256, 256, 0, side>>>(edge_index);
    f2p_gather_kernel<<<(X_ROWS * MAXP + 255) / 256, 256, 0, side>>>(out);
    index_kernel<<<(3 * X_ROWS + 1 + 255) / 256, 256, 0, side>>>(out);
    tok_kernel<<<(6 * N_U + 6 * N_O) / 4, 256, 0, side>>>(
        users_num, users_cat, orders_num, orders_cat,
        u_num_w, u_num_b, u_cat_tab, u_col,
        o_num_w, o_num_b, o_cat_tab, o_col,
        table_emb, out);
    if (s2) cudaEventRecord(evJoin, s2);

    // ---- main branch: W split + fused GEMM ----
    w_split_kernel<<<(CDIM * TXTD + 255) / 256, 256>>>(u_txt_w, o_txt_w);
    txt_gemm_mma<<<GEMM_GRID, 256, SM_TOT>>>(
        users_text, orders_text,
        u_txt_b, u_col, o_txt_b, o_col, table_emb, out);

    if (s2) cudaStreamWaitEvent(0, evJoin, 0);
}

// round 8
// speedup vs baseline: 4.0728x; 1.0962x over previous
#include <cuda_runtime.h>
#include <cuda_bf16.h>
#include <cstdint>

// ---------------- problem constants ----------------
#define N_U      20000
#define N_O      10000
#define N_TOT    30000
#define CDIM     256
#define TXTD     1536
#define NCOLS    7
#define E_EDGES  10000
#define MAXP     16
#define NUM_NODES 30000
#define VOCAB    101

#define X_ROWS   210000
#define OFF_NODE 53760000
#define OFF_COL  53970000
#define OFF_TAB  54180000
#define OFF_F2P  54390000
#define OFF_NN   57750000

// ---------------- device scratch ----------------
__device__ int g_tbl[NUM_NODES * MAXP];
__device__ int g_cnt[N_O];
__device__ int g_slot[N_O * 32];
__device__ __nv_bfloat16 g_w_hi[2 * CDIM * TXTD];
__device__ __nv_bfloat16 g_w_lo[2 * CDIM * TXTD];

// ---------------- helpers ----------------
__device__ __forceinline__ uint32_t smem_u32(const void* p) {
    uint32_t a;
    asm("{ .reg .u64 t; cvta.to.shared.u64 t, %1; cvt.u32.u64 %0, t; }" : "=r"(a) : "l"(p));
    return a;
}

__device__ __forceinline__ void split2(float a, float b, uint32_t& h, uint32_t& l) {
    __nv_bfloat162 hb = __floats2bfloat162_rn(a, b);
    float fa = __bfloat162float(hb.x);
    float fb = __bfloat162float(hb.y);
    __nv_bfloat162 lb = __floats2bfloat162_rn(a - fa, b - fb);
    h = *reinterpret_cast<uint32_t*>(&hb);
    l = *reinterpret_cast<uint32_t*>(&lb);
}

#define LDSM_X4(r0, r1, r2, r3, addr) \
    asm volatile("ldmatrix.sync.aligned.m8n8.x4.shared.b16 {%0,%1,%2,%3}, [%4];" \
        : "=r"(r0), "=r"(r1), "=r"(r2), "=r"(r3) : "r"(addr))

#define MMA16816(d, a, b0, b1) \
    asm volatile("mma.sync.aligned.m16n8k16.row.col.f32.bf16.bf16.f32 " \
        "{%0,%1,%2,%3}, {%4,%5,%6,%7}, {%8,%9}, {%0,%1,%2,%3};" \
        : "+f"((d)[0]), "+f"((d)[1]), "+f"((d)[2]), "+f"((d)[3]) \
        : "r"((a)[0]), "r"((a)[1]), "r"((a)[2]), "r"((a)[3]), "r"(b0), "r"(b1))

__device__ __forceinline__ void cp16(uint32_t dst, const void* src, int pred_sz) {
    asm volatile("cp.async.cg.shared.global [%0], [%1], 16, %2;"
                 :: "r"(dst), "l"(src), "r"(pred_sz));
}
#define CP_COMMIT() asm volatile("cp.async.commit_group;" ::: "memory")
#define CP_WAIT0()  asm volatile("cp.async.wait_group 0;" ::: "memory")

// ---------------- init scratch ----------------
__global__ void init_scratch_kernel() {
    int i = blockIdx.x * blockDim.x + threadIdx.x;
    if (i < NUM_NODES * MAXP) g_tbl[i] = -1;
    if (i < N_O) g_cnt[i] = 0;
}

// ---------------- W split ----------------
__global__ void w_split_kernel(const float* __restrict__ uw, const float* __restrict__ ow) {
    int i = blockIdx.x * blockDim.x + threadIdx.x;
    if (i >= CDIM * TXTD) return;
    int idx = i * 2;
    float a, b;
    if (idx < CDIM * TXTD) { a = uw[idx]; b = uw[idx + 1]; }
    else { a = ow[idx - CDIM * TXTD]; b = ow[idx - CDIM * TXTD + 1]; }
    uint32_t h, l;
    split2(a, b, h, l);
    *(uint32_t*)&g_w_hi[idx] = h;
    *(uint32_t*)&g_w_lo[idx] = l;
}

// ---------------- edges: scatter + per-child sort ----------------
__global__ void edge_scatter_kernel(const int* __restrict__ edge_index) {
    int i = blockIdx.x * blockDim.x + threadIdx.x;
    if (i >= E_EDGES) return;
    int c = edge_index[i];
    int s = atomicAdd(&g_cnt[c], 1);
    if (s < 32) g_slot[c * 32 + s] = i;
}

__global__ void edge_sort_write_kernel(const int* __restrict__ edge_index) {
    int c = blockIdx.x * blockDim.x + threadIdx.x;
    if (c >= N_O) return;
    int n = g_cnt[c];
    if (n > 32) n = 32;
    int idx[32];
    for (int j = 0; j < n; j++) {
        int v = g_slot[c * 32 + j];
        int pos = j;
        while (pos > 0 && idx[pos - 1] > v) { idx[pos] = idx[pos - 1]; pos--; }
        idx[pos] = v;
    }
    int lim = n < MAXP ? n : MAXP;
    for (int r = 0; r < lim; r++)
        g_tbl[(N_U + c) * MAXP + r] = edge_index[E_EDGES + idx[r]];
}

// ---------------- f2p gather ----------------
__global__ void f2p_gather_kernel(float* __restrict__ out) {
    int i = blockIdx.x * blockDim.x + threadIdx.x;
    if (i >= X_ROWS * MAXP) return;
    int row = i >> 4;
    int s = i & (MAXP - 1);
    int node;
    if (row < NCOLS * N_U) node = row % N_U;
    else                   node = N_U + (row - NCOLS * N_U) % N_O;
    out[OFF_F2P + i] = (float)g_tbl[node * MAXP + s];
}

// ---------------- index arrays + num_nodes ----------------
__global__ void index_kernel(float* __restrict__ out) {
    int i = blockIdx.x * blockDim.x + threadIdx.x;
    if (i > 3 * X_ROWS) return;
    if (i == 3 * X_ROWS) { out[OFF_NN] = (float)NUM_NODES; return; }
    int r = i / X_ROWS;
    int j = i - r * X_ROWS;
    int node, colv, tabv;
    if (j < NCOLS * N_U) {
        node = j % N_U; colv = j / N_U; tabv = 0;
    } else {
        int jj = j - NCOLS * N_U;
        node = N_U + jj % N_O; colv = NCOLS + jj / N_O; tabv = 1;
    }
    if      (r == 0) out[OFF_NODE + j] = (float)node;
    else if (r == 1) out[OFF_COL  + j] = (float)colv;
    else             out[OFF_TAB  + j] = (float)tabv;
}

// ---------------- num + cat tokens ----------------
__global__ void tok_kernel(
    const float* __restrict__ unum, const int* __restrict__ ucat,
    const float* __restrict__ onum, const int* __restrict__ ocat,
    const float* __restrict__ u_nw, const float* __restrict__ u_nb,
    const float* __restrict__ u_ct, const float* __restrict__ u_col,
    const float* __restrict__ o_nw, const float* __restrict__ o_nb,
    const float* __restrict__ o_ct, const float* __restrict__ o_col,
    const float* __restrict__ temb, float* __restrict__ out)
{
    int rid = blockIdx.x * 4 + (threadIdx.x >> 6);
    int c4 = (threadIdx.x & 63) * 4;
    int k, n, row;
    const float *nw, *nb, *ct, *col, *te, *nump;
    const int* catp;
    if (rid < 6 * N_U) {
        k = rid / N_U; n = rid - k * N_U;
        row = k * N_U + n;
        nw = u_nw; nb = u_nb; ct = u_ct; col = u_col; te = temb;
        nump = unum; catp = ucat;
    } else {
        int b = rid - 6 * N_U;
        k = b / N_O; n = b - k * N_O;
        row = NCOLS * N_U + k * N_O + n;
        nw = o_nw; nb = o_nb; ct = o_ct; col = o_col; te = temb + CDIM;
        nump = onum; catp = ocat;
    }
    float4 v;
    if (k < 3) {
        float x = nump[n * 3 + k];
        float4 w = *(const float4*)&nw[k * CDIM + c4];
        float4 bb = *(const float4*)&nb[k * CDIM + c4];
        float z0 = x * w.x + bb.x, z1 = x * w.y + bb.y;
        float z2 = x * w.z + bb.z, z3 = x * w.w + bb.w;
        v.x = z0 / (1.0f + __expf(-z0));
        v.y = z1 / (1.0f + __expf(-z1));
        v.z = z2 / (1.0f + __expf(-z2));
        v.w = z3 / (1.0f + __expf(-z3));
    } else {
        int idx = catp[n * 3 + (k - 3)];
        v = *(const float4*)&ct[((k - 3) * VOCAB + idx) * CDIM + c4];
    }
    float4 cv = *(const float4*)&col[k * CDIM + c4];
    float4 tv = *(const float4*)&te[c4];
    v.x += cv.x + tv.x; v.y += cv.y + tv.y;
    v.z += cv.z + tv.z; v.w += cv.w + tv.w;
    *(float4*)&out[(size_t)row * CDIM + c4] = v;
}

// ---------------- persistent full-width fused-split bf16 HMMA text GEMM ----------------
// 512 threads, CTA tile 128x256, warps 4(m) x 4(n), warp tile 32x64.
// A loaded fp32 + split in-kernel ONCE per tile; B via cp.async from pre-split W.
// One __syncthreads per chunk; B cp.async for ch+1 issued AFTER the barrier
// (all warps done reading stage s^1) -- fixes the round-7 WAR race.
#define U_TILES 157
#define O_TILES 79
#define NTILES  (U_TILES + O_TILES)
#define GEMM_GRID 148
#define BK      32
#define ROWB    80
#define TILEB_A (128 * ROWB)           // 10240
#define TILEB_B (256 * ROWB)           // 20480
#define STAGEB  (2 * TILEB_A + 2 * TILEB_B)   // 61440
#define SM_BIAS (2 * STAGEB)           // 122880
#define SM_TOT  (SM_BIAS + 1024)
#define KCH     (TXTD / BK)            // 48

__global__ void __launch_bounds__(512, 1) txt_gemm_mma(
    const float* __restrict__ uA, const float* __restrict__ oA,
    const float* __restrict__ u_tb, const float* __restrict__ u_col,
    const float* __restrict__ o_tb, const float* __restrict__ o_col,
    const float* __restrict__ temb, float* __restrict__ out)
{
    extern __shared__ char smem[];
    uint32_t sb = smem_u32(smem);

    int tid = threadIdx.x;
    int lane = tid & 31;
    int wid = tid >> 5;
    int warp_m = wid & 3;        // 0..3 -> 32-row slice
    int warp_n = wid >> 2;       // 0..3 -> 64-col slice

    // A load geometry: row = tid>>2 (0..127), 8 fp32 at (tid&3)*8
    int a_r  = tid >> 2;
    int a_c8 = (tid & 3) * 8;
    uint32_t a_sts = (uint32_t)(a_r * ROWB + a_c8 * 2);

    // B load geometry: 2 groups of 16B per thread per (hi|lo)
    int r0 = tid >> 2,         cs0 = tid & 3;
    int r1 = (tid + 512) >> 2, cs1 = (tid + 512) & 3;
    uint32_t d0 = (uint32_t)(r0 * ROWB + cs0 * 16);
    uint32_t d1 = (uint32_t)(r1 * ROWB + cs1 * 16);

    // ldmatrix lane-invariant offsets
    uint32_t a_row = (uint32_t)(warp_m * 32 + (lane & 15));
    uint32_t a_ch  = (uint32_t)(lane >> 4);
    uint32_t b_row = (uint32_t)(warp_n * 64 + (lane & 7) + ((lane >> 4) << 3));
    uint32_t b_ch  = (uint32_t)((lane >> 3) & 1);

    float* s_bias = (float*)(smem + SM_BIAS);

    for (int tile = blockIdx.x; tile < NTILES; tile += GEMM_GRID) {
        const float* A;
        int M, m0, orow0, wrow0;
        const float *tb, *col, *te;
        if (tile < U_TILES) {
            A = uA; M = N_U; m0 = tile * 128; orow0 = 6 * N_U; wrow0 = 0;
            tb = u_tb; col = u_col; te = temb;
        } else {
            A = oA; M = N_O; m0 = (tile - U_TILES) * 128;
            orow0 = NCOLS * N_U + 6 * N_O; wrow0 = CDIM;
            tb = o_tb; col = o_col; te = temb + CDIM;
        }

        if (tid < 256) {
            s_bias[tid] = tb[tid] + col[6 * CDIM + tid] + te[tid];
        }

        float acc[2][8][4];
        #pragma unroll
        for (int mi = 0; mi < 2; mi++)
            #pragma unroll
            for (int nt = 0; nt < 8; nt++)
                #pragma unroll
                for (int q = 0; q < 4; q++) acc[mi][nt][q] = 0.0f;

        int a_gr = m0 + a_r;
        bool a_ok = (a_gr < M);
        const float* a_ptr = A + (size_t)(a_ok ? a_gr : 0) * TXTD + a_c8;

        size_t boff0 = (size_t)(wrow0 + r0) * TXTD + cs0 * 8;
        size_t boff1 = (size_t)(wrow0 + r1) * TXTD + cs1 * 8;

        auto load_B = [&](int s, int ch) {
            int k0 = ch * BK;
            uint32_t base = sb + s * STAGEB + 2 * TILEB_A;
            cp16(base + d0,           &g_w_hi[boff0 + k0], 16);
            cp16(base + d1,           &g_w_hi[boff1 + k0], 16);
            cp16(base + TILEB_B + d0, &g_w_lo[boff0 + k0], 16);
            cp16(base + TILEB_B + d1, &g_w_lo[boff1 + k0], 16);
            CP_COMMIT();
        };

        // prefetch A chunk 0 + B chunk 0
        float4 av0, av1;
        {
            const float4* p = (const float4*)a_ptr;
            if (a_ok) { av0 = p[0]; av1 = p[1]; }
            else { av0 = av1 = make_float4(0.f, 0.f, 0.f, 0.f); }
        }
        load_B(0, 0);

        for (int ch = 0; ch < KCH; ch++) {
            int s = ch & 1;
            CP_WAIT0();   // stage-s B (issued last chunk / preamble) has landed

            // convert prefetched A -> hi/lo SMEM (stage s)
            // safe: all warps passed the PREVIOUS chunk's barrier => chunk ch-2's
            // stage-s reads are complete.
            {
                uint32_t base = sb + s * STAGEB;
                uint4 h, l;
                split2(av0.x, av0.y, h.x, l.x);
                split2(av0.z, av0.w, h.y, l.y);
                split2(av1.x, av1.y, h.z, l.z);
                split2(av1.z, av1.w, h.w, l.w);
                asm volatile("st.shared.v4.b32 [%0], {%1,%2,%3,%4};" ::
                    "r"(base + a_sts), "r"(h.x), "r"(h.y), "r"(h.z), "r"(h.w));
                asm volatile("st.shared.v4.b32 [%0], {%1,%2,%3,%4};" ::
                    "r"(base + TILEB_A + a_sts), "r"(l.x), "r"(l.y), "r"(l.z), "r"(l.w));
            }
            // prefetch A for next chunk
            if (ch + 1 < KCH) {
                const float4* p = (const float4*)(a_ptr + (ch + 1) * BK);
                if (a_ok) { av0 = p[0]; av1 = p[1]; }
            }
            __syncthreads();   // stage s fully written; stage s^1 fully READ by all

            // now safe to overwrite stage s^1 B
            if (ch + 1 < KCH) load_B(s ^ 1, ch + 1);

            uint32_t sa_hi = sb + s * STAGEB;
            uint32_t sa_lo = sa_hi + TILEB_A;
            uint32_t sbh   = sa_hi + 2 * TILEB_A;
            uint32_t sbl   = sbh + TILEB_B;

            #pragma unroll
            for (int ks = 0; ks < 2; ks++) {
                uint32_t a_off = a_row * ROWB + (2 * ks + a_ch) * 16;
                uint32_t b_off = b_row * ROWB + (2 * ks + b_ch) * 16;

                uint32_t ah[2][4], bh[4][4];
                #pragma unroll
                for (int mi = 0; mi < 2; mi++)
                    LDSM_X4(ah[mi][0], ah[mi][1], ah[mi][2], ah[mi][3],
                            sa_hi + a_off + mi * 16 * ROWB);
                #pragma unroll
                for (int np = 0; np < 4; np++)
                    LDSM_X4(bh[np][0], bh[np][1], bh[np][2], bh[np][3],
                            sbh + b_off + np * 16 * ROWB);
                #pragma unroll
                for (int mi = 0; mi < 2; mi++)
                    #pragma unroll
                    for (int np = 0; np < 4; np++) {
                        MMA16816(acc[mi][2 * np],     ah[mi], bh[np][0], bh[np][1]);
                        MMA16816(acc[mi][2 * np + 1], ah[mi], bh[np][2], bh[np][3]);
                    }

                uint32_t al[2][4];
                #pragma unroll
                for (int mi = 0; mi < 2; mi++)
                    LDSM_X4(al[mi][0], al[mi][1], al[mi][2], al[mi][3],
                            sa_lo + a_off + mi * 16 * ROWB);
                #pragma unroll
                for (int mi = 0; mi < 2; mi++)
                    #pragma unroll
                    for (int np = 0; np < 4; np++) {
                        MMA16816(acc[mi][2 * np],     al[mi], bh[np][0], bh[np][1]);
                        MMA16816(acc[mi][2 * np + 1], al[mi], bh[np][2], bh[np][3]);
                    }

                uint32_t bl[4][4];
                #pragma unroll
                for (int np = 0; np < 4; np++)
                    LDSM_X4(bl[np][0], bl[np][1], bl[np][2], bl[np][3],
                            sbl + b_off + np * 16 * ROWB);
                #pragma unroll
                for (int mi = 0; mi < 2; mi++)
                    #pragma unroll
                    for (int np = 0; np < 4; np++) {
                        MMA16816(acc[mi][2 * np],     ah[mi], bl[np][0], bl[np][1]);
                        MMA16816(acc[mi][2 * np + 1], ah[mi], bl[np][2], bl[np][3]);
                    }
            }
        }

        // epilogue
        #pragma unroll
        for (int mi = 0; mi < 2; mi++) {
            #pragma unroll
            for (int rh = 0; rh < 2; rh++) {
                int row = m0 + warp_m * 32 + mi * 16 + (lane >> 2) + rh * 8;
                if (row >= M) continue;
                size_t rbase = (size_t)(orow0 + row) * CDIM;
                #pragma unroll
                for (int nt = 0; nt < 8; nt++) {
                    int cc = warp_n * 64 + nt * 8 + (lane & 3) * 2;
                    float2 o;
                    o.x = acc[mi][nt][rh * 2 + 0] + s_bias[cc];
                    o.y = acc[mi][nt][rh * 2 + 1] + s_bias[cc + 1];
                    *(float2*)&out[rbase + cc] = o;
                }
            }
        }
        __syncthreads();   // all reads of s_bias + all stage reads done before next tile
    }
}

// ---------------- launch ----------------
extern "C" void kernel_launch(void* const* d_in, const int* in_sizes, int n_in,
                              void* d_out, int out_size) {
    const float* users_num   = (const float*)d_in[0];
    const int*   users_cat   = (const int*)  d_in[1];
    const float* users_text  = (const float*)d_in[2];
    const float* orders_num  = (const float*)d_in[3];
    const int*   orders_cat  = (const int*)  d_in[4];
    const float* orders_text = (const float*)d_in[5];
    const int*   edge_index  = (const int*)  d_in[6];
    const float* table_emb   = (const float*)d_in[7];
    const float* u_num_w     = (const float*)d_in[8];
    const float* u_num_b     = (const float*)d_in[9];
    const float* u_cat_tab   = (const float*)d_in[10];
    const float* u_txt_w     = (const float*)d_in[11];
    const float* u_txt_b     = (const float*)d_in[12];
    const float* u_col       = (const float*)d_in[13];
    const float* o_num_w     = (const float*)d_in[14];
    const float* o_num_b     = (const float*)d_in[15];
    const float* o_cat_tab   = (const float*)d_in[16];
    const float* o_txt_w     = (const float*)d_in[17];
    const float* o_txt_b     = (const float*)d_in[18];
    const float* o_col       = (const float*)d_in[19];

    float* out = (float*)d_out;

    // one-time host-side setup (no device allocations)
    static cudaStream_t s2 = nullptr;
    static cudaEvent_t evFork = nullptr, evJoin = nullptr;
    static bool setup_done = false;
    if (!setup_done) {
        cudaFuncSetAttribute(txt_gemm_mma, cudaFuncAttributeMaxDynamicSharedMemorySize, SM_TOT);
        if (cudaStreamCreateWithFlags(&s2, cudaStreamNonBlocking) != cudaSuccess) s2 = nullptr;
        if (s2) {
            cudaEventCreateWithFlags(&evFork, cudaEventDisableTiming);
            cudaEventCreateWithFlags(&evJoin, cudaEventDisableTiming);
        }
        setup_done = true;
    }

    cudaStream_t side = s2 ? s2 : (cudaStream_t)0;
    if (s2) {
        cudaEventRecord(evFork, 0);
        cudaStreamWaitEvent(s2, evFork, 0);
    }

    // ---- side branch: edge table, gathers, indices, tokens ----
    init_scratch_kernel<<<(NUM_NODES * MAXP + 255) / 256, 256, 0, side>>>();
    edge_scatter_kernel<<<(E_EDGES + 255) / 256, 256, 0, side>>>(edge_index);
    edge_sort_write_kernel<<<(N_O + 255) / 256, 256, 0, side>>>(edge_index);
    f2p_gather_kernel<<<(X_ROWS * MAXP + 255) / 256, 256, 0, side>>>(out);
    index_kernel<<<(3 * X_ROWS + 1 + 255) / 256, 256, 0, side>>>(out);
    tok_kernel<<<(6 * N_U + 6 * N_O) / 4, 256, 0, side>>>(
        users_num, users_cat, orders_num, orders_cat,
        u_num_w, u_num_b, u_cat_tab, u_col,
        o_num_w, o_num_b, o_cat_tab, o_col,
        table_emb, out);
    if (s2) cudaEventRecord(evJoin, s2);

    // ---- main branch: W split + fused GEMM ----
    w_split_kernel<<<(CDIM * TXTD + 255) / 256, 256>>>(u_txt_w, o_txt_w);
    txt_gemm_mma<<<GEMM_GRID, 512, SM_TOT>>>(
        users_text, orders_text,
        u_txt_b, u_col, o_txt_b, o_col, table_emb, out);

    if (s2) cudaStreamWaitEvent(0, evJoin, 0);
}

// round 9
// speedup vs baseline: 5.5067x; 1.3521x over previous
#include <cuda_runtime.h>
#include <cuda_fp16.h>
#include <cstdint>

// ---------------- problem constants ----------------
#define N_U      20000
#define N_O      10000
#define N_TOT    30000
#define CDIM     256
#define TXTD     1536
#define NCOLS    7
#define E_EDGES  10000
#define MAXP     16
#define NUM_NODES 30000
#define VOCAB    101

#define X_ROWS   210000
#define OFF_NODE 53760000
#define OFF_COL  53970000
#define OFF_TAB  54180000
#define OFF_F2P  54390000
#define OFF_NN   57750000

// ---------------- device scratch ----------------
__device__ int g_tbl[NUM_NODES * MAXP];
__device__ int g_cnt[N_O];
__device__ int g_slot[N_O * 32];
__device__ __half g_w_h[2 * CDIM * TXTD];   // W rounded to fp16 (rows 0..255 users, 256..511 orders)

// ---------------- helpers ----------------
__device__ __forceinline__ uint32_t smem_u32(const void* p) {
    uint32_t a;
    asm("{ .reg .u64 t; cvta.to.shared.u64 t, %1; cvt.u32.u64 %0, t; }" : "=r"(a) : "l"(p));
    return a;
}

// fp32 pair -> fp16 hi pair + fp16 lo (residual) pair
__device__ __forceinline__ void split2h(float a, float b, uint32_t& h, uint32_t& l) {
    __half2 hh = __floats2half2_rn(a, b);
    float fa = __low2float(hh);
    float fb = __high2float(hh);
    __half2 ll = __floats2half2_rn(a - fa, b - fb);
    h = *reinterpret_cast<uint32_t*>(&hh);
    l = *reinterpret_cast<uint32_t*>(&ll);
}

#define LDSM_X4(r0, r1, r2, r3, addr) \
    asm volatile("ldmatrix.sync.aligned.m8n8.x4.shared.b16 {%0,%1,%2,%3}, [%4];" \
        : "=r"(r0), "=r"(r1), "=r"(r2), "=r"(r3) : "r"(addr))

#define MMA16816H(d, a, b0, b1) \
    asm volatile("mma.sync.aligned.m16n8k16.row.col.f32.f16.f16.f32 " \
        "{%0,%1,%2,%3}, {%4,%5,%6,%7}, {%8,%9}, {%0,%1,%2,%3};" \
        : "+f"((d)[0]), "+f"((d)[1]), "+f"((d)[2]), "+f"((d)[3]) \
        : "r"((a)[0]), "r"((a)[1]), "r"((a)[2]), "r"((a)[3]), "r"(b0), "r"(b1))

__device__ __forceinline__ void cp16(uint32_t dst, const void* src, int pred_sz) {
    asm volatile("cp.async.cg.shared.global [%0], [%1], 16, %2;"
                 :: "r"(dst), "l"(src), "r"(pred_sz));
}
#define CP_COMMIT() asm volatile("cp.async.commit_group;" ::: "memory")
#define CP_WAIT0()  asm volatile("cp.async.wait_group 0;" ::: "memory")

// ---------------- init scratch ----------------
__global__ void init_scratch_kernel() {
    int i = blockIdx.x * blockDim.x + threadIdx.x;
    if (i < NUM_NODES * MAXP) g_tbl[i] = -1;
    if (i < N_O) g_cnt[i] = 0;
}

// ---------------- W -> fp16 ----------------
__global__ void w_h_kernel(const float* __restrict__ uw, const float* __restrict__ ow) {
    int i = blockIdx.x * blockDim.x + threadIdx.x;   // pair index
    if (i >= CDIM * TXTD) return;
    int idx = i * 2;
    float a, b;
    if (idx < CDIM * TXTD) { a = uw[idx]; b = uw[idx + 1]; }
    else { a = ow[idx - CDIM * TXTD]; b = ow[idx - CDIM * TXTD + 1]; }
    __half2 h = __floats2half2_rn(a, b);
    *(uint32_t*)&g_w_h[idx] = *reinterpret_cast<uint32_t*>(&h);
}

// ---------------- edges: scatter + per-child sort ----------------
__global__ void edge_scatter_kernel(const int* __restrict__ edge_index) {
    int i = blockIdx.x * blockDim.x + threadIdx.x;
    if (i >= E_EDGES) return;
    int c = edge_index[i];
    int s = atomicAdd(&g_cnt[c], 1);
    if (s < 32) g_slot[c * 32 + s] = i;
}

__global__ void edge_sort_write_kernel(const int* __restrict__ edge_index) {
    int c = blockIdx.x * blockDim.x + threadIdx.x;
    if (c >= N_O) return;
    int n = g_cnt[c];
    if (n > 32) n = 32;
    int idx[32];
    for (int j = 0; j < n; j++) {
        int v = g_slot[c * 32 + j];
        int pos = j;
        while (pos > 0 && idx[pos - 1] > v) { idx[pos] = idx[pos - 1]; pos--; }
        idx[pos] = v;
    }
    int lim = n < MAXP ? n : MAXP;
    for (int r = 0; r < lim; r++)
        g_tbl[(N_U + c) * MAXP + r] = edge_index[E_EDGES + idx[r]];
}

// ---------------- f2p gather ----------------
__global__ void f2p_gather_kernel(float* __restrict__ out) {
    int i = blockIdx.x * blockDim.x + threadIdx.x;
    if (i >= X_ROWS * MAXP) return;
    int row = i >> 4;
    int s = i & (MAXP - 1);
    int node;
    if (row < NCOLS * N_U) node = row % N_U;
    else                   node = N_U + (row - NCOLS * N_U) % N_O;
    out[OFF_F2P + i] = (float)g_tbl[node * MAXP + s];
}

// ---------------- index arrays + num_nodes ----------------
__global__ void index_kernel(float* __restrict__ out) {
    int i = blockIdx.x * blockDim.x + threadIdx.x;
    if (i > 3 * X_ROWS) return;
    if (i == 3 * X_ROWS) { out[OFF_NN] = (float)NUM_NODES; return; }
    int r = i / X_ROWS;
    int j = i - r * X_ROWS;
    int node, colv, tabv;
    if (j < NCOLS * N_U) {
        node = j % N_U; colv = j / N_U; tabv = 0;
    } else {
        int jj = j - NCOLS * N_U;
        node = N_U + jj % N_O; colv = NCOLS + jj / N_O; tabv = 1;
    }
    if      (r == 0) out[OFF_NODE + j] = (float)node;
    else if (r == 1) out[OFF_COL  + j] = (float)colv;
    else             out[OFF_TAB  + j] = (float)tabv;
}

// ---------------- num + cat tokens ----------------
__global__ void tok_kernel(
    const float* __restrict__ unum, const int* __restrict__ ucat,
    const float* __restrict__ onum, const int* __restrict__ ocat,
    const float* __restrict__ u_nw, const float* __restrict__ u_nb,
    const float* __restrict__ u_ct, const float* __restrict__ u_col,
    const float* __restrict__ o_nw, const float* __restrict__ o_nb,
    const float* __restrict__ o_ct, const float* __restrict__ o_col,
    const float* __restrict__ temb, float* __restrict__ out)
{
    int rid = blockIdx.x * 4 + (threadIdx.x >> 6);
    int c4 = (threadIdx.x & 63) * 4;
    int k, n, row;
    const float *nw, *nb, *ct, *col, *te, *nump;
    const int* catp;
    if (rid < 6 * N_U) {
        k = rid / N_U; n = rid - k * N_U;
        row = k * N_U + n;
        nw = u_nw; nb = u_nb; ct = u_ct; col = u_col; te = temb;
        nump = unum; catp = ucat;
    } else {
        int b = rid - 6 * N_U;
        k = b / N_O; n = b - k * N_O;
        row = NCOLS * N_U + k * N_O + n;
        nw = o_nw; nb = o_nb; ct = o_ct; col = o_col; te = temb + CDIM;
        nump = onum; catp = ocat;
    }
    float4 v;
    if (k < 3) {
        float x = nump[n * 3 + k];
        float4 w = *(const float4*)&nw[k * CDIM + c4];
        float4 bb = *(const float4*)&nb[k * CDIM + c4];
        float z0 = x * w.x + bb.x, z1 = x * w.y + bb.y;
        float z2 = x * w.z + bb.z, z3 = x * w.w + bb.w;
        v.x = z0 / (1.0f + __expf(-z0));
        v.y = z1 / (1.0f + __expf(-z1));
        v.z = z2 / (1.0f + __expf(-z2));
        v.w = z3 / (1.0f + __expf(-z3));
    } else {
        int idx = catp[n * 3 + (k - 3)];
        v = *(const float4*)&ct[((k - 3) * VOCAB + idx) * CDIM + c4];
    }
    float4 cv = *(const float4*)&col[k * CDIM + c4];
    float4 tv = *(const float4*)&te[c4];
    v.x += cv.x + tv.x; v.y += cv.y + tv.y;
    v.z += cv.z + tv.z; v.w += cv.w + tv.w;
    *(float4*)&out[(size_t)row * CDIM + c4] = v;
}

// ---------------- persistent fp16 2-term HMMA text GEMM ----------------
// 512 threads, CTA tile 128x256, warps 4(m) x 4(n), warp tile 32x64.
// A = Ah + Al (fp16 pair, exact to ~2^-22); B single-rounded fp16.
// D = Ah*B + Al*B. A loaded fp32 + split in-kernel once per tile.
#define U_TILES 157
#define O_TILES 79
#define NTILES  (U_TILES + O_TILES)
#define GEMM_GRID 148
#define BK      32
#define ROWB    80
#define TILEB_A (128 * ROWB)                  // 10240
#define TILEB_B (256 * ROWB)                  // 20480
#define STAGEB  (2 * TILEB_A + TILEB_B)       // 40960
#define SM_BIAS (2 * STAGEB)                  // 81920
#define SM_TOT  (SM_BIAS + 1024)
#define KCH     (TXTD / BK)                   // 48

__global__ void __launch_bounds__(512, 1) txt_gemm_mma(
    const float* __restrict__ uA, const float* __restrict__ oA,
    const float* __restrict__ u_tb, const float* __restrict__ u_col,
    const float* __restrict__ o_tb, const float* __restrict__ o_col,
    const float* __restrict__ temb, float* __restrict__ out)
{
    extern __shared__ char smem[];
    uint32_t sb = smem_u32(smem);

    int tid = threadIdx.x;
    int lane = tid & 31;
    int wid = tid >> 5;
    int warp_m = wid & 3;
    int warp_n = wid >> 2;

    // A load geometry: row = tid>>2 (0..127), 8 fp32 at (tid&3)*8
    int a_r  = tid >> 2;
    int a_c8 = (tid & 3) * 8;
    uint32_t a_sts = (uint32_t)(a_r * ROWB + a_c8 * 2);

    // B load geometry: 2 groups of 16B per thread (hi only)
    int r0 = tid >> 2,         cs0 = tid & 3;
    int r1 = (tid + 512) >> 2, cs1 = (tid + 512) & 3;
    uint32_t d0 = (uint32_t)(r0 * ROWB + cs0 * 16);
    uint32_t d1 = (uint32_t)(r1 * ROWB + cs1 * 16);

    // ldmatrix lane-invariant offsets
    uint32_t a_row = (uint32_t)(warp_m * 32 + (lane & 15));
    uint32_t a_ch  = (uint32_t)(lane >> 4);
    uint32_t b_row = (uint32_t)(warp_n * 64 + (lane & 7) + ((lane >> 4) << 3));
    uint32_t b_ch  = (uint32_t)((lane >> 3) & 1);

    float* s_bias = (float*)(smem + SM_BIAS);

    for (int tile = blockIdx.x; tile < NTILES; tile += GEMM_GRID) {
        const float* A;
        int M, m0, orow0, wrow0;
        const float *tb, *col, *te;
        if (tile < U_TILES) {
            A = uA; M = N_U; m0 = tile * 128; orow0 = 6 * N_U; wrow0 = 0;
            tb = u_tb; col = u_col; te = temb;
        } else {
            A = oA; M = N_O; m0 = (tile - U_TILES) * 128;
            orow0 = NCOLS * N_U + 6 * N_O; wrow0 = CDIM;
            tb = o_tb; col = o_col; te = temb + CDIM;
        }

        if (tid < 256) {
            s_bias[tid] = tb[tid] + col[6 * CDIM + tid] + te[tid];
        }

        float acc[2][8][4];
        #pragma unroll
        for (int mi = 0; mi < 2; mi++)
            #pragma unroll
            for (int nt = 0; nt < 8; nt++)
                #pragma unroll
                for (int q = 0; q < 4; q++) acc[mi][nt][q] = 0.0f;

        int a_gr = m0 + a_r;
        bool a_ok = (a_gr < M);
        const float* a_ptr = A + (size_t)(a_ok ? a_gr : 0) * TXTD + a_c8;

        size_t boff0 = (size_t)(wrow0 + r0) * TXTD + cs0 * 8;
        size_t boff1 = (size_t)(wrow0 + r1) * TXTD + cs1 * 8;

        auto load_B = [&](int s, int ch) {
            int k0 = ch * BK;
            uint32_t base = sb + s * STAGEB + 2 * TILEB_A;
            cp16(base + d0, &g_w_h[boff0 + k0], 16);
            cp16(base + d1, &g_w_h[boff1 + k0], 16);
            CP_COMMIT();
        };

        // prefetch A chunk 0 + B chunk 0
        float4 av0, av1;
        {
            const float4* p = (const float4*)a_ptr;
            if (a_ok) { av0 = p[0]; av1 = p[1]; }
            else { av0 = av1 = make_float4(0.f, 0.f, 0.f, 0.f); }
        }
        load_B(0, 0);

        for (int ch = 0; ch < KCH; ch++) {
            int s = ch & 1;
            CP_WAIT0();   // stage-s B has landed

            // convert prefetched A -> hi/lo fp16 SMEM (stage s)
            {
                uint32_t base = sb + s * STAGEB;
                uint4 h, l;
                split2h(av0.x, av0.y, h.x, l.x);
                split2h(av0.z, av0.w, h.y, l.y);
                split2h(av1.x, av1.y, h.z, l.z);
                split2h(av1.z, av1.w, h.w, l.w);
                asm volatile("st.shared.v4.b32 [%0], {%1,%2,%3,%4};" ::
                    "r"(base + a_sts), "r"(h.x), "r"(h.y), "r"(h.z), "r"(h.w));
                asm volatile("st.shared.v4.b32 [%0], {%1,%2,%3,%4};" ::
                    "r"(base + TILEB_A + a_sts), "r"(l.x), "r"(l.y), "r"(l.z), "r"(l.w));
            }
            // prefetch A for next chunk
            if (ch + 1 < KCH) {
                const float4* p = (const float4*)(a_ptr + (ch + 1) * BK);
                if (a_ok) { av0 = p[0]; av1 = p[1]; }
            }
            __syncthreads();   // stage s written; stage s^1 fully read by all warps

            if (ch + 1 < KCH) load_B(s ^ 1, ch + 1);

            uint32_t sa_hi = sb + s * STAGEB;
            uint32_t sa_lo = sa_hi + TILEB_A;
            uint32_t sbh   = sa_hi + 2 * TILEB_A;

            #pragma unroll
            for (int ks = 0; ks < 2; ks++) {
                uint32_t a_off = a_row * ROWB + (2 * ks + a_ch) * 16;
                uint32_t b_off = b_row * ROWB + (2 * ks + b_ch) * 16;

                uint32_t ah[2][4], bh[4][4];
                #pragma unroll
                for (int mi = 0; mi < 2; mi++)
                    LDSM_X4(ah[mi][0], ah[mi][1], ah[mi][2], ah[mi][3],
                            sa_hi + a_off + mi * 16 * ROWB);
                #pragma unroll
                for (int np = 0; np < 4; np++)
                    LDSM_X4(bh[np][0], bh[np][1], bh[np][2], bh[np][3],
                            sbh + b_off + np * 16 * ROWB);
                #pragma unroll
                for (int mi = 0; mi < 2; mi++)
                    #pragma unroll
                    for (int np = 0; np < 4; np++) {
                        MMA16816H(acc[mi][2 * np],     ah[mi], bh[np][0], bh[np][1]);
                        MMA16816H(acc[mi][2 * np + 1], ah[mi], bh[np][2], bh[np][3]);
                    }

                uint32_t al[2][4];
                #pragma unroll
                for (int mi = 0; mi < 2; mi++)
                    LDSM_X4(al[mi][0], al[mi][1], al[mi][2], al[mi][3],
                            sa_lo + a_off + mi * 16 * ROWB);
                #pragma unroll
                for (int mi = 0; mi < 2; mi++)
                    #pragma unroll
                    for (int np = 0; np < 4; np++) {
                        MMA16816H(acc[mi][2 * np],     al[mi], bh[np][0], bh[np][1]);
                        MMA16816H(acc[mi][2 * np + 1], al[mi], bh[np][2], bh[np][3]);
                    }
            }
        }

        // epilogue
        #pragma unroll
        for (int mi = 0; mi < 2; mi++) {
            #pragma unroll
            for (int rh = 0; rh < 2; rh++) {
                int row = m0 + warp_m * 32 + mi * 16 + (lane >> 2) + rh * 8;
                if (row >= M) continue;
                size_t rbase = (size_t)(orow0 + row) * CDIM;
                #pragma unroll
                for (int nt = 0; nt < 8; nt++) {
                    int cc = warp_n * 64 + nt * 8 + (lane & 3) * 2;
                    float2 o;
                    o.x = acc[mi][nt][rh * 2 + 0] + s_bias[cc];
                    o.y = acc[mi][nt][rh * 2 + 1] + s_bias[cc + 1];
                    *(float2*)&out[rbase + cc] = o;
                }
            }
        }
        __syncthreads();
    }
}

// ---------------- launch ----------------
extern "C" void kernel_launch(void* const* d_in, const int* in_sizes, int n_in,
                              void* d_out, int out_size) {
    const float* users_num   = (const float*)d_in[0];
    const int*   users_cat   = (const int*)  d_in[1];
    const float* users_text  = (const float*)d_in[2];
    const float* orders_num  = (const float*)d_in[3];
    const int*   orders_cat  = (const int*)  d_in[4];
    const float* orders_text = (const float*)d_in[5];
    const int*   edge_index  = (const int*)  d_in[6];
    const float* table_emb   = (const float*)d_in[7];
    const float* u_num_w     = (const float*)d_in[8];
    const float* u_num_b     = (const float*)d_in[9];
    const float* u_cat_tab   = (const float*)d_in[10];
    const float* u_txt_w     = (const float*)d_in[11];
    const float* u_txt_b     = (const float*)d_in[12];
    const float* u_col       = (const float*)d_in[13];
    const float* o_num_w     = (const float*)d_in[14];
    const float* o_num_b     = (const float*)d_in[15];
    const float* o_cat_tab   = (const float*)d_in[16];
    const float* o_txt_w     = (const float*)d_in[17];
    const float* o_txt_b     = (const float*)d_in[18];
    const float* o_col       = (const float*)d_in[19];

    float* out = (float*)d_out;

    // one-time host-side setup (no device allocations)
    static cudaStream_t s2 = nullptr;
    static cudaEvent_t evFork = nullptr, evJoin = nullptr;
    static bool setup_done = false;
    if (!setup_done) {
        cudaFuncSetAttribute(txt_gemm_mma, cudaFuncAttributeMaxDynamicSharedMemorySize, SM_TOT);
        if (cudaStreamCreateWithFlags(&s2, cudaStreamNonBlocking) != cudaSuccess) s2 = nullptr;
        if (s2) {
            cudaEventCreateWithFlags(&evFork, cudaEventDisableTiming);
            cudaEventCreateWithFlags(&evJoin, cudaEventDisableTiming);
        }
        setup_done = true;
    }

    cudaStream_t side = s2 ? s2 : (cudaStream_t)0;
    if (s2) {
        cudaEventRecord(evFork, 0);
        cudaStreamWaitEvent(s2, evFork, 0);
    }

    // ---- side branch: edge table, gathers, indices, tokens ----
    init_scratch_kernel<<<(NUM_NODES * MAXP + 255) / 256, 256, 0, side>>>();
    edge_scatter_kernel<<<(E_EDGES + 255) / 256, 256, 0, side>>>(edge_index);
    edge_sort_write_kernel<<<(N_O + 255) / 256, 256, 0, side>>>(edge_index);
    f2p_gather_kernel<<<(X_ROWS * MAXP + 255) / 256, 256, 0, side>>>(out);
    index_kernel<<<(3 * X_ROWS + 1 + 255) / 256, 256, 0, side>>>(out);
    tok_kernel<<<(6 * N_U + 6 * N_O) / 4, 256, 0, side>>>(
        users_num, users_cat, orders_num, orders_cat,
        u_num_w, u_num_b, u_cat_tab, u_col,
        o_num_w, o_num_b, o_cat_tab, o_col,
        table_emb, out);
    if (s2) cudaEventRecord(evJoin, s2);

    // ---- main branch: W fp16 + fused GEMM ----
    w_h_kernel<<<(CDIM * TXTD + 255) / 256, 256>>>(u_txt_w, o_txt_w);
    txt_gemm_mma<<<GEMM_GRID, 512, SM_TOT>>>(
        users_text, orders_text,
        u_txt_b, u_col, o_txt_b, o_col, table_emb, out);

    if (s2) cudaStreamWaitEvent(0, evJoin, 0);
}

// round 10
// speedup vs baseline: 6.8162x; 1.2378x over previous
#include <cuda_runtime.h>
#include <cuda_fp16.h>
#include <cstdint>

// ---------------- problem constants ----------------
#define N_U      20000
#define N_O      10000
#define N_TOT    30000
#define CDIM     256
#define TXTD     1536
#define NCOLS    7
#define E_EDGES  10000
#define MAXP     16
#define NUM_NODES 30000
#define VOCAB    101

#define X_ROWS   210000
#define OFF_NODE 53760000
#define OFF_COL  53970000
#define OFF_TAB  54180000
#define OFF_F2P  54390000
#define OFF_NN   57750000

// ---------------- device scratch ----------------
__device__ int g_tbl[NUM_NODES * MAXP];
__device__ int g_cnt[N_O];
__device__ int g_slot[N_O * 32];
__device__ __half g_w_h[2 * CDIM * TXTD];   // W rounded to fp16

// ---------------- helpers ----------------
__device__ __forceinline__ uint32_t smem_u32(const void* p) {
    uint32_t a;
    asm("{ .reg .u64 t; cvta.to.shared.u64 t, %1; cvt.u32.u64 %0, t; }" : "=r"(a) : "l"(p));
    return a;
}

#define LDSM_X4(r0, r1, r2, r3, addr) \
    asm volatile("ldmatrix.sync.aligned.m8n8.x4.shared.b16 {%0,%1,%2,%3}, [%4];" \
        : "=r"(r0), "=r"(r1), "=r"(r2), "=r"(r3) : "r"(addr))

#define MMA16816H(d, a, b0, b1) \
    asm volatile("mma.sync.aligned.m16n8k16.row.col.f32.f16.f16.f32 " \
        "{%0,%1,%2,%3}, {%4,%5,%6,%7}, {%8,%9}, {%0,%1,%2,%3};" \
        : "+f"((d)[0]), "+f"((d)[1]), "+f"((d)[2]), "+f"((d)[3]) \
        : "r"((a)[0]), "r"((a)[1]), "r"((a)[2]), "r"((a)[3]), "r"(b0), "r"(b1))

__device__ __forceinline__ void cp16(uint32_t dst, const void* src, int pred_sz) {
    asm volatile("cp.async.cg.shared.global [%0], [%1], 16, %2;"
                 :: "r"(dst), "l"(src), "r"(pred_sz));
}
#define CP_COMMIT() asm volatile("cp.async.commit_group;" ::: "memory")
#define CP_WAIT0()  asm volatile("cp.async.wait_group 0;" ::: "memory")

// ---------------- init scratch ----------------
__global__ void init_scratch_kernel() {
    int i = blockIdx.x * blockDim.x + threadIdx.x;
    if (i < NUM_NODES * MAXP) g_tbl[i] = -1;
    if (i < N_O) g_cnt[i] = 0;
}

// ---------------- W -> fp16 ----------------
__global__ void w_h_kernel(const float* __restrict__ uw, const float* __restrict__ ow) {
    int i = blockIdx.x * blockDim.x + threadIdx.x;
    if (i >= CDIM * TXTD) return;
    int idx = i * 2;
    float a, b;
    if (idx < CDIM * TXTD) { a = uw[idx]; b = uw[idx + 1]; }
    else { a = ow[idx - CDIM * TXTD]; b = ow[idx - CDIM * TXTD + 1]; }
    __half2 h = __floats2half2_rn(a, b);
    *(uint32_t*)&g_w_h[idx] = *reinterpret_cast<uint32_t*>(&h);
}

// ---------------- edges: scatter + per-child sort ----------------
__global__ void edge_scatter_kernel(const int* __restrict__ edge_index) {
    int i = blockIdx.x * blockDim.x + threadIdx.x;
    if (i >= E_EDGES) return;
    int c = edge_index[i];
    int s = atomicAdd(&g_cnt[c], 1);
    if (s < 32) g_slot[c * 32 + s] = i;
}

__global__ void edge_sort_write_kernel(const int* __restrict__ edge_index) {
    int c = blockIdx.x * blockDim.x + threadIdx.x;
    if (c >= N_O) return;
    int n = g_cnt[c];
    if (n > 32) n = 32;
    int idx[32];
    for (int j = 0; j < n; j++) {
        int v = g_slot[c * 32 + j];
        int pos = j;
        while (pos > 0 && idx[pos - 1] > v) { idx[pos] = idx[pos - 1]; pos--; }
        idx[pos] = v;
    }
    int lim = n < MAXP ? n : MAXP;
    for (int r = 0; r < lim; r++)
        g_tbl[(N_U + c) * MAXP + r] = edge_index[E_EDGES + idx[r]];
}

// ---------------- f2p gather ----------------
__global__ void f2p_gather_kernel(float* __restrict__ out) {
    int i = blockIdx.x * blockDim.x + threadIdx.x;
    if (i >= X_ROWS * MAXP) return;
    int row = i >> 4;
    int s = i & (MAXP - 1);
    int node;
    if (row < NCOLS * N_U) node = row % N_U;
    else                   node = N_U + (row - NCOLS * N_U) % N_O;
    out[OFF_F2P + i] = (float)g_tbl[node * MAXP + s];
}

// ---------------- index arrays + num_nodes ----------------
__global__ void index_kernel(float* __restrict__ out) {
    int i = blockIdx.x * blockDim.x + threadIdx.x;
    if (i > 3 * X_ROWS) return;
    if (i == 3 * X_ROWS) { out[OFF_NN] = (float)NUM_NODES; return; }
    int r = i / X_ROWS;
    int j = i - r * X_ROWS;
    int node, colv, tabv;
    if (j < NCOLS * N_U) {
        node = j % N_U; colv = j / N_U; tabv = 0;
    } else {
        int jj = j - NCOLS * N_U;
        node = N_U + jj % N_O; colv = NCOLS + jj / N_O; tabv = 1;
    }
    if      (r == 0) out[OFF_NODE + j] = (float)node;
    else if (r == 1) out[OFF_COL  + j] = (float)colv;
    else             out[OFF_TAB  + j] = (float)tabv;
}

// ---------------- num + cat tokens ----------------
__global__ void tok_kernel(
    const float* __restrict__ unum, const int* __restrict__ ucat,
    const float* __restrict__ onum, const int* __restrict__ ocat,
    const float* __restrict__ u_nw, const float* __restrict__ u_nb,
    const float* __restrict__ u_ct, const float* __restrict__ u_col,
    const float* __restrict__ o_nw, const float* __restrict__ o_nb,
    const float* __restrict__ o_ct, const float* __restrict__ o_col,
    const float* __restrict__ temb, float* __restrict__ out)
{
    int rid = blockIdx.x * 4 + (threadIdx.x >> 6);
    int c4 = (threadIdx.x & 63) * 4;
    int k, n, row;
    const float *nw, *nb, *ct, *col, *te, *nump;
    const int* catp;
    if (rid < 6 * N_U) {
        k = rid / N_U; n = rid - k * N_U;
        row = k * N_U + n;
        nw = u_nw; nb = u_nb; ct = u_ct; col = u_col; te = temb;
        nump = unum; catp = ucat;
    } else {
        int b = rid - 6 * N_U;
        k = b / N_O; n = b - k * N_O;
        row = NCOLS * N_U + k * N_O + n;
        nw = o_nw; nb = o_nb; ct = o_ct; col = o_col; te = temb + CDIM;
        nump = onum; catp = ocat;
    }
    float4 v;
    if (k < 3) {
        float x = nump[n * 3 + k];
        float4 w = *(const float4*)&nw[k * CDIM + c4];
        float4 bb = *(const float4*)&nb[k * CDIM + c4];
        float z0 = x * w.x + bb.x, z1 = x * w.y + bb.y;
        float z2 = x * w.z + bb.z, z3 = x * w.w + bb.w;
        v.x = z0 / (1.0f + __expf(-z0));
        v.y = z1 / (1.0f + __expf(-z1));
        v.z = z2 / (1.0f + __expf(-z2));
        v.w = z3 / (1.0f + __expf(-z3));
    } else {
        int idx = catp[n * 3 + (k - 3)];
        v = *(const float4*)&ct[((k - 3) * VOCAB + idx) * CDIM + c4];
    }
    float4 cv = *(const float4*)&col[k * CDIM + c4];
    float4 tv = *(const float4*)&te[c4];
    v.x += cv.x + tv.x; v.y += cv.y + tv.y;
    v.z += cv.z + tv.z; v.w += cv.w + tv.w;
    *(float4*)&out[(size_t)row * CDIM + c4] = v;
}

// ---------------- persistent fp16 1-term HMMA text GEMM ----------------
// 512 threads, CTA tile 128x256, warps 4(m) x 4(n), warp tile 32x64.
// A and B both single-rounded fp16 (calibrated combined rel_err ~2.9e-4 < 1e-3).
#define U_TILES 157
#define O_TILES 79
#define NTILES  (U_TILES + O_TILES)
#define GEMM_GRID 148
#define BK      32
#define ROWB    80
#define TILEB_A (128 * ROWB)             // 10240
#define TILEB_B (256 * ROWB)             // 20480
#define STAGEB  (TILEB_A + TILEB_B)      // 30720
#define SM_BIAS (2 * STAGEB)             // 61440
#define SM_TOT  (SM_BIAS + 1024)
#define KCH     (TXTD / BK)              // 48

__global__ void __launch_bounds__(512, 1) txt_gemm_mma(
    const float* __restrict__ uA, const float* __restrict__ oA,
    const float* __restrict__ u_tb, const float* __restrict__ u_col,
    const float* __restrict__ o_tb, const float* __restrict__ o_col,
    const float* __restrict__ temb, float* __restrict__ out)
{
    extern __shared__ char smem[];
    uint32_t sb = smem_u32(smem);

    int tid = threadIdx.x;
    int lane = tid & 31;
    int wid = tid >> 5;
    int warp_m = wid & 3;
    int warp_n = wid >> 2;

    // A load geometry: row = tid>>2 (0..127), 8 fp32 at (tid&3)*8
    int a_r  = tid >> 2;
    int a_c8 = (tid & 3) * 8;
    uint32_t a_sts = (uint32_t)(a_r * ROWB + a_c8 * 2);

    // B load geometry: 2 groups of 16B per thread
    int r0 = tid >> 2,         cs0 = tid & 3;
    int r1 = (tid + 512) >> 2, cs1 = (tid + 512) & 3;
    uint32_t d0 = (uint32_t)(r0 * ROWB + cs0 * 16);
    uint32_t d1 = (uint32_t)(r1 * ROWB + cs1 * 16);

    // ldmatrix lane-invariant offsets
    uint32_t a_row = (uint32_t)(warp_m * 32 + (lane & 15));
    uint32_t a_ch  = (uint32_t)(lane >> 4);
    uint32_t b_row = (uint32_t)(warp_n * 64 + (lane & 7) + ((lane >> 4) << 3));
    uint32_t b_ch  = (uint32_t)((lane >> 3) & 1);

    float* s_bias = (float*)(smem + SM_BIAS);

    for (int tile = blockIdx.x; tile < NTILES; tile += GEMM_GRID) {
        const float* A;
        int M, m0, orow0, wrow0;
        const float *tb, *col, *te;
        if (tile < U_TILES) {
            A = uA; M = N_U; m0 = tile * 128; orow0 = 6 * N_U; wrow0 = 0;
            tb = u_tb; col = u_col; te = temb;
        } else {
            A = oA; M = N_O; m0 = (tile - U_TILES) * 128;
            orow0 = NCOLS * N_U + 6 * N_O; wrow0 = CDIM;
            tb = o_tb; col = o_col; te = temb + CDIM;
        }

        if (tid < 256) {
            s_bias[tid] = tb[tid] + col[6 * CDIM + tid] + te[tid];
        }

        float acc[2][8][4];
        #pragma unroll
        for (int mi = 0; mi < 2; mi++)
            #pragma unroll
            for (int nt = 0; nt < 8; nt++)
                #pragma unroll
                for (int q = 0; q < 4; q++) acc[mi][nt][q] = 0.0f;

        int a_gr = m0 + a_r;
        bool a_ok = (a_gr < M);
        const float* a_ptr = A + (size_t)(a_ok ? a_gr : 0) * TXTD + a_c8;

        size_t boff0 = (size_t)(wrow0 + r0) * TXTD + cs0 * 8;
        size_t boff1 = (size_t)(wrow0 + r1) * TXTD + cs1 * 8;

        auto load_B = [&](int s, int ch) {
            int k0 = ch * BK;
            uint32_t base = sb + s * STAGEB + TILEB_A;
            cp16(base + d0, &g_w_h[boff0 + k0], 16);
            cp16(base + d1, &g_w_h[boff1 + k0], 16);
            CP_COMMIT();
        };

        // prefetch A chunk 0 + B chunk 0
        float4 av0, av1;
        {
            const float4* p = (const float4*)a_ptr;
            if (a_ok) { av0 = p[0]; av1 = p[1]; }
            else { av0 = av1 = make_float4(0.f, 0.f, 0.f, 0.f); }
        }
        load_B(0, 0);

        for (int ch = 0; ch < KCH; ch++) {
            int s = ch & 1;
            CP_WAIT0();   // stage-s B has landed

            // convert prefetched A -> fp16 SMEM (stage s)
            {
                uint32_t base = sb + s * STAGEB;
                __half2 h0 = __floats2half2_rn(av0.x, av0.y);
                __half2 h1 = __floats2half2_rn(av0.z, av0.w);
                __half2 h2 = __floats2half2_rn(av1.x, av1.y);
                __half2 h3 = __floats2half2_rn(av1.z, av1.w);
                asm volatile("st.shared.v4.b32 [%0], {%1,%2,%3,%4};" ::
                    "r"(base + a_sts),
                    "r"(*reinterpret_cast<uint32_t*>(&h0)),
                    "r"(*reinterpret_cast<uint32_t*>(&h1)),
                    "r"(*reinterpret_cast<uint32_t*>(&h2)),
                    "r"(*reinterpret_cast<uint32_t*>(&h3)));
            }
            // prefetch A for next chunk
            if (ch + 1 < KCH) {
                const float4* p = (const float4*)(a_ptr + (ch + 1) * BK);
                if (a_ok) { av0 = p[0]; av1 = p[1]; }
            }
            __syncthreads();   // stage s written; stage s^1 fully read by all warps

            if (ch + 1 < KCH) load_B(s ^ 1, ch + 1);

            uint32_t sa = sb + s * STAGEB;
            uint32_t sbh = sa + TILEB_A;

            #pragma unroll
            for (int ks = 0; ks < 2; ks++) {
                uint32_t a_off = a_row * ROWB + (2 * ks + a_ch) * 16;
                uint32_t b_off = b_row * ROWB + (2 * ks + b_ch) * 16;

                uint32_t ah[2][4], bh[4][4];
                #pragma unroll
                for (int mi = 0; mi < 2; mi++)
                    LDSM_X4(ah[mi][0], ah[mi][1], ah[mi][2], ah[mi][3],
                            sa + a_off + mi * 16 * ROWB);
                #pragma unroll
                for (int np = 0; np < 4; np++)
                    LDSM_X4(bh[np][0], bh[np][1], bh[np][2], bh[np][3],
                            sbh + b_off + np * 16 * ROWB);
                #pragma unroll
                for (int mi = 0; mi < 2; mi++)
                    #pragma unroll
                    for (int np = 0; np < 4; np++) {
                        MMA16816H(acc[mi][2 * np],     ah[mi], bh[np][0], bh[np][1]);
                        MMA16816H(acc[mi][2 * np + 1], ah[mi], bh[np][2], bh[np][3]);
                    }
            }
        }

        // epilogue
        #pragma unroll
        for (int mi = 0; mi < 2; mi++) {
            #pragma unroll
            for (int rh = 0; rh < 2; rh++) {
                int row = m0 + warp_m * 32 + mi * 16 + (lane >> 2) + rh * 8;
                if (row >= M) continue;
                size_t rbase = (size_t)(orow0 + row) * CDIM;
                #pragma unroll
                for (int nt = 0; nt < 8; nt++) {
                    int cc = warp_n * 64 + nt * 8 + (lane & 3) * 2;
                    float2 o;
                    o.x = acc[mi][nt][rh * 2 + 0] + s_bias[cc];
                    o.y = acc[mi][nt][rh * 2 + 1] + s_bias[cc + 1];
                    *(float2*)&out[rbase + cc] = o;
                }
            }
        }
        __syncthreads();
    }
}

// ---------------- launch ----------------
extern "C" void kernel_launch(void* const* d_in, const int* in_sizes, int n_in,
                              void* d_out, int out_size) {
    const float* users_num   = (const float*)d_in[0];
    const int*   users_cat   = (const int*)  d_in[1];
    const float* users_text  = (const float*)d_in[2];
    const float* orders_num  = (const float*)d_in[3];
    const int*   orders_cat  = (const int*)  d_in[4];
    const float* orders_text = (const float*)d_in[5];
    const int*   edge_index  = (const int*)  d_in[6];
    const float* table_emb   = (const float*)d_in[7];
    const float* u_num_w     = (const float*)d_in[8];
    const float* u_num_b     = (const float*)d_in[9];
    const float* u_cat_tab   = (const float*)d_in[10];
    const float* u_txt_w     = (const float*)d_in[11];
    const float* u_txt_b     = (const float*)d_in[12];
    const float* u_col       = (const float*)d_in[13];
    const float* o_num_w     = (const float*)d_in[14];
    const float* o_num_b     = (const float*)d_in[15];
    const float* o_cat_tab   = (const float*)d_in[16];
    const float* o_txt_w     = (const float*)d_in[17];
    const float* o_txt_b     = (const float*)d_in[18];
    const float* o_col       = (const float*)d_in[19];

    float* out = (float*)d_out;

    // one-time host-side setup (no device allocations)
    static cudaStream_t s2 = nullptr;
    static cudaEvent_t evFork = nullptr, evJoin = nullptr;
    static bool setup_done = false;
    if (!setup_done) {
        cudaFuncSetAttribute(txt_gemm_mma, cudaFuncAttributeMaxDynamicSharedMemorySize, SM_TOT);
        if (cudaStreamCreateWithFlags(&s2, cudaStreamNonBlocking) != cudaSuccess) s2 = nullptr;
        if (s2) {
            cudaEventCreateWithFlags(&evFork, cudaEventDisableTiming);
            cudaEventCreateWithFlags(&evJoin, cudaEventDisableTiming);
        }
        setup_done = true;
    }

    cudaStream_t side = s2 ? s2 : (cudaStream_t)0;
    if (s2) {
        cudaEventRecord(evFork, 0);
        cudaStreamWaitEvent(s2, evFork, 0);
    }

    // ---- side branch: edge table, gathers, indices, tokens ----
    init_scratch_kernel<<<(NUM_NODES * MAXP + 255) / 256, 256, 0, side>>>();
    edge_scatter_kernel<<<(E_EDGES + 255) / 256, 256, 0, side>>>(edge_index);
    edge_sort_write_kernel<<<(N_O + 255) / 256, 256, 0, side>>>(edge_index);
    f2p_gather_kernel<<<(X_ROWS * MAXP + 255) / 256, 256, 0, side>>>(out);
    index_kernel<<<(3 * X_ROWS + 1 + 255) / 256, 256, 0, side>>>(out);
    tok_kernel<<<(6 * N_U + 6 * N_O) / 4, 256, 0, side>>>(
        users_num, users_cat, orders_num, orders_cat,
        u_num_w, u_num_b, u_cat_tab, u_col,
        o_num_w, o_num_b, o_cat_tab, o_col,
        table_emb, out);
    if (s2) cudaEventRecord(evJoin, s2);

    // ---- main branch: W fp16 + fused GEMM ----
    w_h_kernel<<<(CDIM * TXTD + 255) / 256, 256>>>(u_txt_w, o_txt_w);
    txt_gemm_mma<<<GEMM_GRID, 512, SM_TOT>>>(
        users_text, orders_text,
        u_txt_b, u_col, o_txt_b, o_col, table_emb, out);

    if (s2) cudaStreamWaitEvent(0, evJoin, 0);
}

// round 11
// speedup vs baseline: 7.1037x; 1.0422x over previous
#include <cuda_runtime.h>
#include <cuda_fp16.h>
#include <cstdint>

// ---------------- problem constants ----------------
#define N_U      20000
#define N_O      10000
#define N_TOT    30000
#define CDIM     256
#define TXTD     1536
#define NCOLS    7
#define E_EDGES  10000
#define MAXP     16
#define NUM_NODES 30000
#define VOCAB    101

#define X_ROWS   210000
#define OFF_NODE 53760000
#define OFF_COL  53970000
#define OFF_TAB  54180000
#define OFF_F2P  54390000
#define OFF_NN   57750000

// ---------------- device scratch ----------------
__device__ int g_tbl[NUM_NODES * MAXP];
__device__ int g_cnt[N_O];
__device__ int g_slot[N_O * 32];
__device__ __half g_w_h[2 * CDIM * TXTD];   // W rounded to fp16

// ---------------- helpers ----------------
__device__ __forceinline__ uint32_t smem_u32(const void* p) {
    uint32_t a;
    asm("{ .reg .u64 t; cvta.to.shared.u64 t, %1; cvt.u32.u64 %0, t; }" : "=r"(a) : "l"(p));
    return a;
}

#define LDSM_X4(r0, r1, r2, r3, addr) \
    asm volatile("ldmatrix.sync.aligned.m8n8.x4.shared.b16 {%0,%1,%2,%3}, [%4];" \
        : "=r"(r0), "=r"(r1), "=r"(r2), "=r"(r3) : "r"(addr))

#define MMA16816H(d, a, b0, b1) \
    asm volatile("mma.sync.aligned.m16n8k16.row.col.f32.f16.f16.f32 " \
        "{%0,%1,%2,%3}, {%4,%5,%6,%7}, {%8,%9}, {%0,%1,%2,%3};" \
        : "+f"((d)[0]), "+f"((d)[1]), "+f"((d)[2]), "+f"((d)[3]) \
        : "r"((a)[0]), "r"((a)[1]), "r"((a)[2]), "r"((a)[3]), "r"(b0), "r"(b1))

__device__ __forceinline__ void cp16(uint32_t dst, const void* src, int pred_sz) {
    asm volatile("cp.async.cg.shared.global [%0], [%1], 16, %2;"
                 :: "r"(dst), "l"(src), "r"(pred_sz));
}
#define CP_COMMIT() asm volatile("cp.async.commit_group;" ::: "memory")
#define CP_WAIT1()  asm volatile("cp.async.wait_group 1;" ::: "memory")
#define CP_WAIT0()  asm volatile("cp.async.wait_group 0;" ::: "memory")

// ---------------- init scratch ----------------
__global__ void init_scratch_kernel() {
    int i = blockIdx.x * blockDim.x + threadIdx.x;
    if (i < NUM_NODES * MAXP) g_tbl[i] = -1;
    if (i < N_O) g_cnt[i] = 0;
}

// ---------------- W -> fp16 ----------------
__global__ void w_h_kernel(const float* __restrict__ uw, const float* __restrict__ ow) {
    int i = blockIdx.x * blockDim.x + threadIdx.x;
    if (i >= CDIM * TXTD) return;
    int idx = i * 2;
    float a, b;
    if (idx < CDIM * TXTD) { a = uw[idx]; b = uw[idx + 1]; }
    else { a = ow[idx - CDIM * TXTD]; b = ow[idx - CDIM * TXTD + 1]; }
    __half2 h = __floats2half2_rn(a, b);
    *(uint32_t*)&g_w_h[idx] = *reinterpret_cast<uint32_t*>(&h);
}

// ---------------- edges: scatter + per-child sort ----------------
__global__ void edge_scatter_kernel(const int* __restrict__ edge_index) {
    int i = blockIdx.x * blockDim.x + threadIdx.x;
    if (i >= E_EDGES) return;
    int c = edge_index[i];
    int s = atomicAdd(&g_cnt[c], 1);
    if (s < 32) g_slot[c * 32 + s] = i;
}

__global__ void edge_sort_write_kernel(const int* __restrict__ edge_index) {
    int c = blockIdx.x * blockDim.x + threadIdx.x;
    if (c >= N_O) return;
    int n = g_cnt[c];
    if (n > 32) n = 32;
    int idx[32];
    for (int j = 0; j < n; j++) {
        int v = g_slot[c * 32 + j];
        int pos = j;
        while (pos > 0 && idx[pos - 1] > v) { idx[pos] = idx[pos - 1]; pos--; }
        idx[pos] = v;
    }
    int lim = n < MAXP ? n : MAXP;
    for (int r = 0; r < lim; r++)
        g_tbl[(N_U + c) * MAXP + r] = edge_index[E_EDGES + idx[r]];
}

// ---------------- f2p gather ----------------
__global__ void f2p_gather_kernel(float* __restrict__ out) {
    int i = blockIdx.x * blockDim.x + threadIdx.x;
    if (i >= X_ROWS * MAXP) return;
    int row = i >> 4;
    int s = i & (MAXP - 1);
    int node;
    if (row < NCOLS * N_U) node = row % N_U;
    else                   node = N_U + (row - NCOLS * N_U) % N_O;
    out[OFF_F2P + i] = (float)g_tbl[node * MAXP + s];
}

// ---------------- index arrays + num_nodes ----------------
__global__ void index_kernel(float* __restrict__ out) {
    int i = blockIdx.x * blockDim.x + threadIdx.x;
    if (i > 3 * X_ROWS) return;
    if (i == 3 * X_ROWS) { out[OFF_NN] = (float)NUM_NODES; return; }
    int r = i / X_ROWS;
    int j = i - r * X_ROWS;
    int node, colv, tabv;
    if (j < NCOLS * N_U) {
        node = j % N_U; colv = j / N_U; tabv = 0;
    } else {
        int jj = j - NCOLS * N_U;
        node = N_U + jj % N_O; colv = NCOLS + jj / N_O; tabv = 1;
    }
    if      (r == 0) out[OFF_NODE + j] = (float)node;
    else if (r == 1) out[OFF_COL  + j] = (float)colv;
    else             out[OFF_TAB  + j] = (float)tabv;
}

// ---------------- num + cat tokens ----------------
__global__ void tok_kernel(
    const float* __restrict__ unum, const int* __restrict__ ucat,
    const float* __restrict__ onum, const int* __restrict__ ocat,
    const float* __restrict__ u_nw, const float* __restrict__ u_nb,
    const float* __restrict__ u_ct, const float* __restrict__ u_col,
    const float* __restrict__ o_nw, const float* __restrict__ o_nb,
    const float* __restrict__ o_ct, const float* __restrict__ o_col,
    const float* __restrict__ temb, float* __restrict__ out)
{
    int rid = blockIdx.x * 4 + (threadIdx.x >> 6);
    int c4 = (threadIdx.x & 63) * 4;
    int k, n, row;
    const float *nw, *nb, *ct, *col, *te, *nump;
    const int* catp;
    if (rid < 6 * N_U) {
        k = rid / N_U; n = rid - k * N_U;
        row = k * N_U + n;
        nw = u_nw; nb = u_nb; ct = u_ct; col = u_col; te = temb;
        nump = unum; catp = ucat;
    } else {
        int b = rid - 6 * N_U;
        k = b / N_O; n = b - k * N_O;
        row = NCOLS * N_U + k * N_O + n;
        nw = o_nw; nb = o_nb; ct = o_ct; col = o_col; te = temb + CDIM;
        nump = onum; catp = ocat;
    }
    float4 v;
    if (k < 3) {
        float x = nump[n * 3 + k];
        float4 w = *(const float4*)&nw[k * CDIM + c4];
        float4 bb = *(const float4*)&nb[k * CDIM + c4];
        float z0 = x * w.x + bb.x, z1 = x * w.y + bb.y;
        float z2 = x * w.z + bb.z, z3 = x * w.w + bb.w;
        v.x = z0 / (1.0f + __expf(-z0));
        v.y = z1 / (1.0f + __expf(-z1));
        v.z = z2 / (1.0f + __expf(-z2));
        v.w = z3 / (1.0f + __expf(-z3));
    } else {
        int idx = catp[n * 3 + (k - 3)];
        v = *(const float4*)&ct[((k - 3) * VOCAB + idx) * CDIM + c4];
    }
    float4 cv = *(const float4*)&col[k * CDIM + c4];
    float4 tv = *(const float4*)&te[c4];
    v.x += cv.x + tv.x; v.y += cv.y + tv.y;
    v.z += cv.z + tv.z; v.w += cv.w + tv.w;
    *(float4*)&out[(size_t)row * CDIM + c4] = v;
}

// ---------------- persistent fp16 HMMA text GEMM (BK=64, 3-stage B) ----------------
// 512 threads, CTA tile 128x256, warps 4(m) x 4(n), warp tile 32x64.
// A: fp32 reg-prefetch -> fp16 cvt -> 2-stage SMEM.  B: cp.async, 3-stage,
// issued 2 chunks ahead (wait_group 1 at loop top is a near-no-op).
#define U_TILES 157
#define O_TILES 79
#define NTILES  (U_TILES + O_TILES)
#define GEMM_GRID 148
#define BK      64
#define ROWB    144                      // 128B data + 16B pad (conflict-free LDSM)
#define TILEB_A (128 * ROWB)             // 18432
#define TILEB_B (256 * ROWB)             // 36864
#define SM_B0   (2 * TILEB_A)            // B stages start after 2 A stages
#define SM_BIAS (2 * TILEB_A + 3 * TILEB_B)   // 147456
#define SM_TOT  (SM_BIAS + 1024)
#define KCH     (TXTD / BK)              // 24

__global__ void __launch_bounds__(512, 1) txt_gemm_mma(
    const float* __restrict__ uA, const float* __restrict__ oA,
    const float* __restrict__ u_tb, const float* __restrict__ u_col,
    const float* __restrict__ o_tb, const float* __restrict__ o_col,
    const float* __restrict__ temb, float* __restrict__ out)
{
    extern __shared__ char smem[];
    uint32_t sb = smem_u32(smem);

    int tid = threadIdx.x;
    int lane = tid & 31;
    int wid = tid >> 5;
    int warp_m = wid & 3;
    int warp_n = wid >> 2;

    // A load geometry: row = tid>>2 (0..127), 16 fp32 at (tid&3)*16
    int a_r   = tid >> 2;
    int a_c16 = (tid & 3) * 16;
    uint32_t a_sts = (uint32_t)(a_r * ROWB + a_c16 * 2);

    // B load geometry: 4 groups of 16B per thread (256 rows x 128B)
    int rB[4], csB[4];
    uint32_t dB[4];
    #pragma unroll
    for (int k = 0; k < 4; k++) {
        int g = tid + k * 512;
        rB[k] = g >> 3; csB[k] = g & 7;
        dB[k] = (uint32_t)(rB[k] * ROWB + csB[k] * 16);
    }

    // ldmatrix lane-invariant offsets
    uint32_t a_row = (uint32_t)(warp_m * 32 + (lane & 15));
    uint32_t a_ch  = (uint32_t)(lane >> 4);
    uint32_t b_row = (uint32_t)(warp_n * 64 + (lane & 7) + ((lane >> 4) << 3));
    uint32_t b_ch  = (uint32_t)((lane >> 3) & 1);

    float* s_bias = (float*)(smem + SM_BIAS);

    for (int tile = blockIdx.x; tile < NTILES; tile += GEMM_GRID) {
        const float* A;
        int M, m0, orow0, wrow0;
        const float *tb, *col, *te;
        if (tile < U_TILES) {
            A = uA; M = N_U; m0 = tile * 128; orow0 = 6 * N_U; wrow0 = 0;
            tb = u_tb; col = u_col; te = temb;
        } else {
            A = oA; M = N_O; m0 = (tile - U_TILES) * 128;
            orow0 = NCOLS * N_U + 6 * N_O; wrow0 = CDIM;
            tb = o_tb; col = o_col; te = temb + CDIM;
        }

        if (tid < 256) {
            s_bias[tid] = tb[tid] + col[6 * CDIM + tid] + te[tid];
        }

        float acc[2][8][4];
        #pragma unroll
        for (int mi = 0; mi < 2; mi++)
            #pragma unroll
            for (int nt = 0; nt < 8; nt++)
                #pragma unroll
                for (int q = 0; q < 4; q++) acc[mi][nt][q] = 0.0f;

        int a_gr = m0 + a_r;
        bool a_ok = (a_gr < M);
        const float* a_ptr = A + (size_t)(a_ok ? a_gr : 0) * TXTD + a_c16;

        size_t boff[4];
        #pragma unroll
        for (int k = 0; k < 4; k++)
            boff[k] = (size_t)(wrow0 + rB[k]) * TXTD + csB[k] * 8;

        auto load_B = [&](int s, int ch) {
            int k0 = ch * BK;
            uint32_t base = sb + SM_B0 + s * TILEB_B;
            #pragma unroll
            for (int k = 0; k < 4; k++)
                cp16(base + dB[k], &g_w_h[boff[k] + k0], 16);
            CP_COMMIT();
        };

        // prefetch A chunk 0 + B chunks 0,1
        float4 av0, av1, av2, av3;
        {
            const float4* p = (const float4*)a_ptr;
            if (a_ok) { av0 = p[0]; av1 = p[1]; av2 = p[2]; av3 = p[3]; }
            else { av0 = av1 = av2 = av3 = make_float4(0.f, 0.f, 0.f, 0.f); }
        }
        load_B(0, 0);
        load_B(1, 1);

        for (int ch = 0; ch < KCH; ch++) {
            int as_ = ch & 1;
            int bs  = ch % 3;
            if (ch + 1 < KCH) { CP_WAIT1(); }   // B(ch) done, B(ch+1) may fly
            else              { CP_WAIT0(); }

            // convert prefetched A -> fp16 SMEM (stage as_)
            {
                uint32_t base = sb + as_ * TILEB_A;
                __half2 h0 = __floats2half2_rn(av0.x, av0.y);
                __half2 h1 = __floats2half2_rn(av0.z, av0.w);
                __half2 h2 = __floats2half2_rn(av1.x, av1.y);
                __half2 h3 = __floats2half2_rn(av1.z, av1.w);
                asm volatile("st.shared.v4.b32 [%0], {%1,%2,%3,%4};" ::
                    "r"(base + a_sts),
                    "r"(*reinterpret_cast<uint32_t*>(&h0)),
                    "r"(*reinterpret_cast<uint32_t*>(&h1)),
                    "r"(*reinterpret_cast<uint32_t*>(&h2)),
                    "r"(*reinterpret_cast<uint32_t*>(&h3)));
                __half2 h4 = __floats2half2_rn(av2.x, av2.y);
                __half2 h5 = __floats2half2_rn(av2.z, av2.w);
                __half2 h6 = __floats2half2_rn(av3.x, av3.y);
                __half2 h7 = __floats2half2_rn(av3.z, av3.w);
                asm volatile("st.shared.v4.b32 [%0], {%1,%2,%3,%4};" ::
                    "r"(base + a_sts + 16),
                    "r"(*reinterpret_cast<uint32_t*>(&h4)),
                    "r"(*reinterpret_cast<uint32_t*>(&h5)),
                    "r"(*reinterpret_cast<uint32_t*>(&h6)),
                    "r"(*reinterpret_cast<uint32_t*>(&h7)));
            }
            // prefetch A for next chunk
            if (ch + 1 < KCH) {
                const float4* p = (const float4*)(a_ptr + (ch + 1) * BK);
                if (a_ok) { av0 = p[0]; av1 = p[1]; av2 = p[2]; av3 = p[3]; }
            }
            __syncthreads();   // A(as_) visible; all warps done MMAs of ch-1

            // stage (ch+2)%3 was last read at chunk ch-1 -> safe to overwrite now
            if (ch + 2 < KCH) load_B((ch + 2) % 3, ch + 2);

            uint32_t sa  = sb + as_ * TILEB_A;
            uint32_t sbh = sb + SM_B0 + bs * TILEB_B;

            #pragma unroll
            for (int ks = 0; ks < 4; ks++) {
                uint32_t a_off = a_row * ROWB + (2 * ks + a_ch) * 16;
                uint32_t b_off = b_row * ROWB + (2 * ks + b_ch) * 16;

                uint32_t ah[2][4], bh[4][4];
                #pragma unroll
                for (int mi = 0; mi < 2; mi++)
                    LDSM_X4(ah[mi][0], ah[mi][1], ah[mi][2], ah[mi][3],
                            sa + a_off + mi * 16 * ROWB);
                #pragma unroll
                for (int np = 0; np < 4; np++)
                    LDSM_X4(bh[np][0], bh[np][1], bh[np][2], bh[np][3],
                            sbh + b_off + np * 16 * ROWB);
                #pragma unroll
                for (int mi = 0; mi < 2; mi++)
                    #pragma unroll
                    for (int np = 0; np < 4; np++) {
                        MMA16816H(acc[mi][2 * np],     ah[mi], bh[np][0], bh[np][1]);
                        MMA16816H(acc[mi][2 * np + 1], ah[mi], bh[np][2], bh[np][3]);
                    }
            }
        }

        // epilogue
        #pragma unroll
        for (int mi = 0; mi < 2; mi++) {
            #pragma unroll
            for (int rh = 0; rh < 2; rh++) {
                int row = m0 + warp_m * 32 + mi * 16 + (lane >> 2) + rh * 8;
                if (row >= M) continue;
                size_t rbase = (size_t)(orow0 + row) * CDIM;
                #pragma unroll
                for (int nt = 0; nt < 8; nt++) {
                    int cc = warp_n * 64 + nt * 8 + (lane & 3) * 2;
                    float2 o;
                    o.x = acc[mi][nt][rh * 2 + 0] + s_bias[cc];
                    o.y = acc[mi][nt][rh * 2 + 1] + s_bias[cc + 1];
                    *(float2*)&out[rbase + cc] = o;
                }
            }
        }
        __syncthreads();   // protect s_bias and smem stages before next tile
    }
}

// ---------------- launch ----------------
extern "C" void kernel_launch(void* const* d_in, const int* in_sizes, int n_in,
                              void* d_out, int out_size) {
    const float* users_num   = (const float*)d_in[0];
    const int*   users_cat   = (const int*)  d_in[1];
    const float* users_text  = (const float*)d_in[2];
    const float* orders_num  = (const float*)d_in[3];
    const int*   orders_cat  = (const int*)  d_in[4];
    const float* orders_text = (const float*)d_in[5];
    const int*   edge_index  = (const int*)  d_in[6];
    const float* table_emb   = (const float*)d_in[7];
    const float* u_num_w     = (const float*)d_in[8];
    const float* u_num_b     = (const float*)d_in[9];
    const float* u_cat_tab   = (const float*)d_in[10];
    const float* u_txt_w     = (const float*)d_in[11];
    const float* u_txt_b     = (const float*)d_in[12];
    const float* u_col       = (const float*)d_in[13];
    const float* o_num_w     = (const float*)d_in[14];
    const float* o_num_b     = (const float*)d_in[15];
    const float* o_cat_tab   = (const float*)d_in[16];
    const float* o_txt_w     = (const float*)d_in[17];
    const float* o_txt_b     = (const float*)d_in[18];
    const float* o_col       = (const float*)d_in[19];

    float* out = (float*)d_out;

    // one-time host-side setup (no device allocations)
    static cudaStream_t s2 = nullptr;
    static cudaEvent_t evFork = nullptr, evJoin = nullptr;
    static bool setup_done = false;
    if (!setup_done) {
        cudaFuncSetAttribute(txt_gemm_mma, cudaFuncAttributeMaxDynamicSharedMemorySize, SM_TOT);
        if (cudaStreamCreateWithFlags(&s2, cudaStreamNonBlocking) != cudaSuccess) s2 = nullptr;
        if (s2) {
            cudaEventCreateWithFlags(&evFork, cudaEventDisableTiming);
            cudaEventCreateWithFlags(&evJoin, cudaEventDisableTiming);
        }
        setup_done = true;
    }

    cudaStream_t side = s2 ? s2 : (cudaStream_t)0;
    if (s2) {
        cudaEventRecord(evFork, 0);
        cudaStreamWaitEvent(s2, evFork, 0);
    }

    // ---- side branch: edge table, gathers, indices, tokens ----
    init_scratch_kernel<<<(NUM_NODES * MAXP + 255) / 256, 256, 0, side>>>();
    edge_scatter_kernel<<<(E_EDGES + 255) / 256, 256, 0, side>>>(edge_index);
    edge_sort_write_kernel<<<(N_O + 255) / 256, 256, 0, side>>>(edge_index);
    f2p_gather_kernel<<<(X_ROWS * MAXP + 255) / 256, 256, 0, side>>>(out);
    index_kernel<<<(3 * X_ROWS + 1 + 255) / 256, 256, 0, side>>>(out);
    tok_kernel<<<(6 * N_U + 6 * N_O) / 4, 256, 0, side>>>(
        users_num, users_cat, orders_num, orders_cat,
        u_num_w, u_num_b, u_cat_tab, u_col,
        o_num_w, o_num_b, o_cat_tab, o_col,
        table_emb, out);
    if (s2) cudaEventRecord(evJoin, s2);

    // ---- main branch: W fp16 + fused GEMM ----
    w_h_kernel<<<(CDIM * TXTD + 255) / 256, 256>>>(u_txt_w, o_txt_w);
    txt_gemm_mma<<<GEMM_GRID, 512, SM_TOT>>>(
        users_text, orders_text,
        u_txt_b, u_col, o_txt_b, o_col, table_emb, out);

    if (s2) cudaStreamWaitEvent(0, evJoin, 0);
}